// round 1
// baseline (speedup 1.0000x reference)
#include <cuda_runtime.h>
#include <math.h>

#define SEQ   4096
#define DM    2048
#define NH    16
#define NKV   4
#define HDIM  128
#define QW    (NH * HDIM)   /* 2048 */
#define KWW   (NKV * HDIM)  /* 512  */

// ---- scratch (no allocations allowed; device globals are the sanctioned path) ----
__device__ float g_q[SEQ * QW];
__device__ float g_k[SEQ * KWW];
__device__ float g_v[SEQ * KWW];
__device__ float g_attn[SEQ * QW];

// ============================================================================
// NT SGEMM: C[M,N] = A[M,K] * B[N,K]^T, all row-major fp32.
// 128x128 blocktile, BK=8, 256 threads, 8x8 per thread.
// ============================================================================
__global__ __launch_bounds__(256, 2) void sgemm_nt(
    const float* __restrict__ A, const float* __restrict__ B,
    float* __restrict__ C, int M, int N, int K)
{
    __shared__ float As[8][128];
    __shared__ float Bs[8][128];
    const int tid  = threadIdx.x;
    const int m0   = blockIdx.y * 128;
    const int n0   = blockIdx.x * 128;
    const int lr   = tid >> 1;          // 0..127
    const int lc   = (tid & 1) << 2;    // 0 or 4
    const int trow = (tid >> 4) << 3;   // 0..120
    const int tcol = (tid & 15) << 3;   // 0..120

    float acc[8][8];
#pragma unroll
    for (int i = 0; i < 8; i++)
#pragma unroll
        for (int j = 0; j < 8; j++) acc[i][j] = 0.f;

    const float* Ap = A + (m0 + lr) * K + lc;
    const float* Bp = B + (n0 + lr) * K + lc;

    for (int k0 = 0; k0 < K; k0 += 8) {
        float4 av = *(const float4*)(Ap + k0);
        float4 bv = *(const float4*)(Bp + k0);
        As[lc + 0][lr] = av.x; As[lc + 1][lr] = av.y;
        As[lc + 2][lr] = av.z; As[lc + 3][lr] = av.w;
        Bs[lc + 0][lr] = bv.x; Bs[lc + 1][lr] = bv.y;
        Bs[lc + 2][lr] = bv.z; Bs[lc + 3][lr] = bv.w;
        __syncthreads();
#pragma unroll
        for (int kk = 0; kk < 8; kk++) {
            float af[8], bf[8];
            *(float4*)(af)     = *(const float4*)&As[kk][trow];
            *(float4*)(af + 4) = *(const float4*)&As[kk][trow + 4];
            *(float4*)(bf)     = *(const float4*)&Bs[kk][tcol];
            *(float4*)(bf + 4) = *(const float4*)&Bs[kk][tcol + 4];
#pragma unroll
            for (int i = 0; i < 8; i++)
#pragma unroll
                for (int j = 0; j < 8; j++)
                    acc[i][j] = fmaf(af[i], bf[j], acc[i][j]);
        }
        __syncthreads();
    }
#pragma unroll
    for (int i = 0; i < 8; i++) {
        float* Cp = C + (m0 + trow + i) * N + n0 + tcol;
        *(float4*)(Cp)     = make_float4(acc[i][0], acc[i][1], acc[i][2], acc[i][3]);
        *(float4*)(Cp + 4) = make_float4(acc[i][4], acc[i][5], acc[i][6], acc[i][7]);
    }
}

// ============================================================================
// RoPE: x[s, h, 0:64] / x[s, h, 64:128] rotated; cos/sin are (S,128) with
// cos[d+64]==cos[d] (concat of freqs,freqs in the reference).
// ============================================================================
__global__ void rope_kernel(float* __restrict__ x, const float* __restrict__ cosT,
                            const float* __restrict__ sinT, int nheads)
{
    int idx = blockIdx.x * blockDim.x + threadIdx.x;
    int total = SEQ * nheads * 64;
    if (idx >= total) return;
    int d = idx & 63;
    int h = (idx >> 6) % nheads;
    int s = idx / (nheads << 6);
    float c  = cosT[s * HDIM + d];
    float sn = sinT[s * HDIM + d];
    float* p = x + s * (nheads * HDIM) + h * HDIM;
    float x1 = p[d], x2 = p[d + 64];
    p[d]      = fmaf(x1, c, -x2 * sn);
    p[d + 64] = fmaf(x2, c,  x1 * sn);
}

// ============================================================================
// Causal flash attention, fp32 online softmax.
// Grid: (S/64 q-tiles [reversed for load balance], NH heads), 256 threads.
// Per CTA: Q tile 64x128 resident; loop k-tiles 0..qt; S = Q K^T (4x4 strided
// frags per thread), softmax update, P via smem, O += P V (4 rows x 8 dims).
// ============================================================================
#define QS_STRIDE  132
#define PS_STRIDE  68
#define FLASH_SMEM ((64 * 132 + 64 * 132 + 64 * 128 + 64 * 68) * 4)

__global__ __launch_bounds__(256) void flash_kernel(
    const float* __restrict__ Qg, const float* __restrict__ Kg,
    const float* __restrict__ Vg, float* __restrict__ Og)
{
    extern __shared__ float sm[];
    float* Qs = sm;                    // [64][132]
    float* Ks = sm + 64 * QS_STRIDE;   // [64][132]
    float* Vs = Ks + 64 * QS_STRIDE;   // [64][128]
    float* Ps = Vs + 64 * 128;         // [64][68]

    const int qt    = (int)gridDim.x - 1 - (int)blockIdx.x; // biggest first
    const int h     = blockIdx.y;
    const int kvh   = h >> 2;          // GROUPS = 4
    const int tid   = threadIdx.x;
    const int ty    = tid >> 4;        // 0..15
    const int tx    = tid & 15;        // 0..15
    const int qbase = qt << 6;
    const float scale = 0.08838834764831845f; // 128^-0.5

    // load Q tile (coalesced float4, conflict-free smem stores)
    {
        const float* src = Qg + qbase * QW + h * HDIM;
#pragma unroll
        for (int t = 0; t < 8; t++) {
            int idx = tid + t * 256;
            int r = idx >> 5;
            int c4 = (idx & 31) << 2;
            *(float4*)&Qs[r * QS_STRIDE + c4] = *(const float4*)(src + r * QW + c4);
        }
    }

    float m_run[4], l_run[4], oacc[4][8];
#pragma unroll
    for (int i = 0; i < 4; i++) {
        m_run[i] = -1e30f; l_run[i] = 0.f;
#pragma unroll
        for (int c = 0; c < 8; c++) oacc[i][c] = 0.f;
    }

    for (int kt = 0; kt <= qt; kt++) {
        __syncthreads();   // protect Vs/Ps (prev iter) before overwrite
        {
            const float* ksrc = Kg + (kt << 6) * KWW + kvh * HDIM;
            const float* vsrc = Vg + (kt << 6) * KWW + kvh * HDIM;
#pragma unroll
            for (int t = 0; t < 8; t++) {
                int idx = tid + t * 256;
                int r = idx >> 5;
                int c4 = (idx & 31) << 2;
                *(float4*)&Ks[r * QS_STRIDE + c4] = *(const float4*)(ksrc + r * KWW + c4);
                *(float4*)&Vs[r * 128 + c4]       = *(const float4*)(vsrc + r * KWW + c4);
            }
        }
        __syncthreads();

        // ---- S = Q K^T (rows ty+16i, cols tx+16j) ----
        float acc[4][4];
#pragma unroll
        for (int i = 0; i < 4; i++)
#pragma unroll
            for (int j = 0; j < 4; j++) acc[i][j] = 0.f;

        for (int kk = 0; kk < 128; kk += 4) {
            float4 qf[4], kf[4];
#pragma unroll
            for (int i = 0; i < 4; i++)
                qf[i] = *(const float4*)&Qs[(ty + 16 * i) * QS_STRIDE + kk];
#pragma unroll
            for (int j = 0; j < 4; j++)
                kf[j] = *(const float4*)&Ks[(tx + 16 * j) * QS_STRIDE + kk];
#pragma unroll
            for (int i = 0; i < 4; i++)
#pragma unroll
                for (int j = 0; j < 4; j++) {
                    acc[i][j] = fmaf(qf[i].x, kf[j].x, acc[i][j]);
                    acc[i][j] = fmaf(qf[i].y, kf[j].y, acc[i][j]);
                    acc[i][j] = fmaf(qf[i].z, kf[j].z, acc[i][j]);
                    acc[i][j] = fmaf(qf[i].w, kf[j].w, acc[i][j]);
                }
        }

        // ---- online softmax (row stats shared across the 16 tx lanes) ----
        const int kbase = kt << 6;
#pragma unroll
        for (int i = 0; i < 4; i++) {
            int row = qbase + ty + 16 * i;
            float mt = -1e30f;
#pragma unroll
            for (int j = 0; j < 4; j++) {
                int col = kbase + tx + 16 * j;
                float sc = acc[i][j] * scale;
                if (col > row) sc = -1e30f;
                acc[i][j] = sc;
                mt = fmaxf(mt, sc);
            }
#pragma unroll
            for (int o = 8; o >= 1; o >>= 1)
                mt = fmaxf(mt, __shfl_xor_sync(0xffffffffu, mt, o));
            float mn = fmaxf(m_run[i], mt);
            float alpha = __expf(m_run[i] - mn);
            m_run[i] = mn;
            float rs = 0.f;
#pragma unroll
            for (int j = 0; j < 4; j++) {
                float p = __expf(acc[i][j] - mn);
                rs += p;
                Ps[(ty + 16 * i) * PS_STRIDE + tx + 16 * j] = p;
            }
#pragma unroll
            for (int o = 8; o >= 1; o >>= 1)
                rs += __shfl_xor_sync(0xffffffffu, rs, o);
            l_run[i] = l_run[i] * alpha + rs;
#pragma unroll
            for (int c = 0; c < 8; c++) oacc[i][c] *= alpha;
        }
        __syncthreads();

        // ---- O += P V (rows ty+16i, dims tx*8..tx*8+7) ----
        for (int kk = 0; kk < 64; kk += 4) {
            float4 pf[4];
#pragma unroll
            for (int i = 0; i < 4; i++)
                pf[i] = *(const float4*)&Ps[(ty + 16 * i) * PS_STRIDE + kk];
            float pa[4][4];
#pragma unroll
            for (int i = 0; i < 4; i++) {
                pa[i][0] = pf[i].x; pa[i][1] = pf[i].y;
                pa[i][2] = pf[i].z; pa[i][3] = pf[i].w;
            }
#pragma unroll
            for (int u = 0; u < 4; u++) {
                float4 v0 = *(const float4*)&Vs[(kk + u) * 128 + (tx << 3)];
                float4 v1 = *(const float4*)&Vs[(kk + u) * 128 + (tx << 3) + 4];
#pragma unroll
                for (int i = 0; i < 4; i++) {
                    float p = pa[i][u];
                    oacc[i][0] = fmaf(p, v0.x, oacc[i][0]);
                    oacc[i][1] = fmaf(p, v0.y, oacc[i][1]);
                    oacc[i][2] = fmaf(p, v0.z, oacc[i][2]);
                    oacc[i][3] = fmaf(p, v0.w, oacc[i][3]);
                    oacc[i][4] = fmaf(p, v1.x, oacc[i][4]);
                    oacc[i][5] = fmaf(p, v1.y, oacc[i][5]);
                    oacc[i][6] = fmaf(p, v1.z, oacc[i][6]);
                    oacc[i][7] = fmaf(p, v1.w, oacc[i][7]);
                }
            }
        }
    }

    // epilogue: normalize and store [s, h*128 + d]
#pragma unroll
    for (int i = 0; i < 4; i++) {
        float inv = 1.f / l_run[i];
        int row = qbase + ty + 16 * i;
        float* dst = Og + row * QW + h * HDIM + (tx << 3);
        *(float4*)(dst)     = make_float4(oacc[i][0] * inv, oacc[i][1] * inv,
                                          oacc[i][2] * inv, oacc[i][3] * inv);
        *(float4*)(dst + 4) = make_float4(oacc[i][4] * inv, oacc[i][5] * inv,
                                          oacc[i][6] * inv, oacc[i][7] * inv);
    }
}

// ============================================================================
// Launch: QKV proj -> RoPE(q,k) -> flash attention -> O proj.
// Inputs (metadata order): hidden, cos, sin, attention_mask(unused: causal
// handled analytically, exp(-1e9)==0 in fp32), wq, wk, wv, wo.
// ============================================================================
extern "C" void kernel_launch(void* const* d_in, const int* in_sizes, int n_in,
                              void* d_out, int out_size)
{
    const float* hidden = (const float*)d_in[0];
    const float* cosT   = (const float*)d_in[1];
    const float* sinT   = (const float*)d_in[2];
    const float* wq     = (const float*)d_in[4];
    const float* wk     = (const float*)d_in[5];
    const float* wv     = (const float*)d_in[6];
    const float* wo     = (const float*)d_in[7];
    float* out = (float*)d_out;

    float *qb, *kb, *vb, *ab;
    cudaGetSymbolAddress((void**)&qb, g_q);
    cudaGetSymbolAddress((void**)&kb, g_k);
    cudaGetSymbolAddress((void**)&vb, g_v);
    cudaGetSymbolAddress((void**)&ab, g_attn);

    cudaFuncSetAttribute(flash_kernel,
                         cudaFuncAttributeMaxDynamicSharedMemorySize, FLASH_SMEM);

    sgemm_nt<<<dim3(QW / 128,  SEQ / 128), 256>>>(hidden, wq, qb, SEQ, QW,  DM);
    sgemm_nt<<<dim3(KWW / 128, SEQ / 128), 256>>>(hidden, wk, kb, SEQ, KWW, DM);
    sgemm_nt<<<dim3(KWW / 128, SEQ / 128), 256>>>(hidden, wv, vb, SEQ, KWW, DM);

    rope_kernel<<<(SEQ * NH  * 64 + 255) / 256, 256>>>(qb, cosT, sinT, NH);
    rope_kernel<<<(SEQ * NKV * 64 + 255) / 256, 256>>>(kb, cosT, sinT, NKV);

    flash_kernel<<<dim3(SEQ / 64, NH), 256, FLASH_SMEM>>>(qb, kb, vb, ab);

    sgemm_nt<<<dim3(DM / 128, SEQ / 128), 256>>>(ab, wo, out, SEQ, DM, DM);
}

// round 3
// speedup vs baseline: 1.4640x; 1.4640x over previous
#include <cuda_runtime.h>
#include <cuda_bf16.h>
#include <cstdint>
#include <math.h>

#define SEQ   4096
#define DM    2048
#define NH    16
#define NKV   4
#define HDIM  128
#define QW    (NH * HDIM)    /* 2048 */
#define KWW   (NKV * HDIM)   /* 512  */
#define QKVW  (QW + 2 * KWW) /* 3072 */
#define QKV_STR QKVW

// ---------------- scratch (device globals; no allocations allowed) ----------
__device__ float g_qkv[SEQ * QKVW];          // packed [Q(2048)|K(512)|V(512)]
__device__ float g_attn[SEQ * QW];
__device__ __nv_bfloat16 g_h_hi[SEQ * DM],  g_h_lo[SEQ * DM];
__device__ __nv_bfloat16 g_w_hi[QKVW * DM], g_w_lo[QKVW * DM];
__device__ __nv_bfloat16 g_wo_hi[DM * QW],  g_wo_lo[DM * QW];
__device__ __nv_bfloat16 g_a_hi[SEQ * QW],  g_a_lo[SEQ * QW];

// ---------------- helpers -----------------------------------------------------
__device__ __forceinline__ uint32_t smem_u32(const void* p) {
    uint32_t a;
    asm("{ .reg .u64 t; cvta.to.shared.u64 t, %1; cvt.u32.u64 %0, t; }"
        : "=r"(a) : "l"(p));
    return a;
}

__device__ __forceinline__ void cp16(uint32_t dst, const void* src) {
    asm volatile("cp.async.cg.shared.global [%0], [%1], 16;" :: "r"(dst), "l"(src));
}
#define CP_COMMIT() asm volatile("cp.async.commit_group;" ::: "memory")
#define CP_WAIT(n)  asm volatile("cp.async.wait_group %0;" :: "n"(n) : "memory")

#define LDSM4(r, addr)                                                        \
    asm volatile("ldmatrix.sync.aligned.m8n8.x4.shared.b16 {%0,%1,%2,%3}, [%4];" \
        : "=r"((r)[0]), "=r"((r)[1]), "=r"((r)[2]), "=r"((r)[3]) : "r"(addr))

#define MMA16816(d, a, b)                                                     \
    asm volatile("mma.sync.aligned.m16n8k16.row.col.f32.bf16.bf16.f32 "       \
        "{%0,%1,%2,%3}, {%4,%5,%6,%7}, {%8,%9}, {%0,%1,%2,%3};"               \
        : "+f"((d)[0]), "+f"((d)[1]), "+f"((d)[2]), "+f"((d)[3])              \
        : "r"((a)[0]), "r"((a)[1]), "r"((a)[2]), "r"((a)[3]),                 \
          "r"((b)[0]), "r"((b)[1]))

// ============================================================================
// fp32 -> (bf16 hi, bf16 lo) split. n divisible by 4.
// ============================================================================
__global__ void split_kernel(const float* __restrict__ x,
                             __nv_bfloat16* __restrict__ hi,
                             __nv_bfloat16* __restrict__ lo, int n)
{
    int i = (blockIdx.x * blockDim.x + threadIdx.x) * 4;
    if (i >= n) return;
    float4 v = *(const float4*)(x + i);
    __nv_bfloat16 h0 = __float2bfloat16(v.x);
    __nv_bfloat16 h1 = __float2bfloat16(v.y);
    __nv_bfloat16 h2 = __float2bfloat16(v.z);
    __nv_bfloat16 h3 = __float2bfloat16(v.w);
    __nv_bfloat16 l0 = __float2bfloat16(v.x - __bfloat162float(h0));
    __nv_bfloat16 l1 = __float2bfloat16(v.y - __bfloat162float(h1));
    __nv_bfloat16 l2 = __float2bfloat16(v.z - __bfloat162float(h2));
    __nv_bfloat16 l3 = __float2bfloat16(v.w - __bfloat162float(h3));
    *(__nv_bfloat162*)(hi + i)     = __nv_bfloat162(h0, h1);
    *(__nv_bfloat162*)(hi + i + 2) = __nv_bfloat162(h2, h3);
    *(__nv_bfloat162*)(lo + i)     = __nv_bfloat162(l0, l1);
    *(__nv_bfloat162*)(lo + i + 2) = __nv_bfloat162(l2, l3);
}

// ============================================================================
// Tensor-core (mma.sync bf16) NT GEMM with 3-term split:
//   C[M,N] = Ahi Bhi^T + Ahi Blo^T + Alo Bhi^T   (fp32 accum)
// A: [M,K] bf16 row-major, B: [N,K] bf16 row-major.
// Block 128x128, BK=32, 256 threads (8 warps, 2Mx4N), warp tile 64x32.
// smem rows padded to 40 elems (80B) -> conflict-free ldmatrix.
// ============================================================================
#define BK          32
#define LDS_PAD     40
#define TILE_BYTES  (128 * LDS_PAD * 2)     /* 10240 */
#define STAGE_BYTES (4 * TILE_BYTES)        /* 40960: Ahi,Alo,Bhi,Blo */
#define GEMM_SMEM   (2 * STAGE_BYTES)       /* 81920 */

__global__ __launch_bounds__(256, 1) void gemm_bf16x3(
    const __nv_bfloat16* __restrict__ Ahi, const __nv_bfloat16* __restrict__ Alo,
    const __nv_bfloat16* __restrict__ Bhi, const __nv_bfloat16* __restrict__ Blo,
    float* __restrict__ C, int N, int K)
{
    extern __shared__ char smem[];
    const uint32_t sb = smem_u32(smem);
    const int tid  = threadIdx.x;
    const int wid  = tid >> 5, lane = tid & 31;
    const int m0   = blockIdx.y * 128, n0 = blockIdx.x * 128;
    const int wm   = (wid & 1) * 64;          // warp M offset in tile
    const int wn   = (wid >> 1) * 32;         // warp N offset in tile

    const __nv_bfloat16* srcs[4] = {
        Ahi + (size_t)m0 * K, Alo + (size_t)m0 * K,
        Bhi + (size_t)n0 * K, Blo + (size_t)n0 * K };

    // ldmatrix lane-address components
    const int a_row_l = lane & 15;
    const int a_colb  = ((lane >> 4) & 1) << 3;
    const int b_row_l = (lane & 7) + (((lane >> 4) & 1) << 3);
    const int b_colb  = ((lane >> 3) & 1) << 3;

    float d[4][4][4];
#pragma unroll
    for (int i = 0; i < 4; i++)
#pragma unroll
        for (int j = 0; j < 4; j++)
#pragma unroll
            for (int q = 0; q < 4; q++) d[i][j][q] = 0.f;

    const int nk = K / BK;

    // ---- stage loader: 4 tiles x 128 rows x 32 bf16 (64B/row, 4 chunks) ----
#define LOAD_STAGE(s, k0) do {                                                \
    uint32_t stb = sb + (uint32_t)(s) * STAGE_BYTES;                          \
    _Pragma("unroll")                                                         \
    for (int t = 0; t < 4; t++) {                                             \
        const __nv_bfloat16* src = srcs[t] + (k0);                            \
        uint32_t dstb = stb + (uint32_t)t * TILE_BYTES;                       \
        _Pragma("unroll")                                                     \
        for (int it = 0; it < 2; it++) {                                      \
            int idx = tid + it * 256;                                         \
            int r = idx >> 2, c = idx & 3;                                    \
            cp16(dstb + (uint32_t)(r * LDS_PAD + c * 8) * 2,                  \
                 src + (size_t)r * K + c * 8);                                \
        }                                                                     \
    }                                                                         \
    CP_COMMIT();                                                              \
} while (0)

    LOAD_STAGE(0, 0);

    for (int kt = 0; kt < nk; kt++) {
        if (kt + 1 < nk) { LOAD_STAGE((kt + 1) & 1, (kt + 1) * BK); CP_WAIT(1); }
        else             { CP_WAIT(0); }
        __syncthreads();

        const uint32_t stb  = sb + (uint32_t)(kt & 1) * STAGE_BYTES;
        const uint32_t AhiB = stb;
        const uint32_t AloB = stb + TILE_BYTES;
        const uint32_t BhiB = stb + 2 * TILE_BYTES;
        const uint32_t BloB = stb + 3 * TILE_BYTES;

#pragma unroll
        for (int ks = 0; ks < BK; ks += 16) {
            uint32_t ah[4][4], al[4][4], bh[4][2], bl[4][2];
#pragma unroll
            for (int i = 0; i < 4; i++) {
                uint32_t off = (uint32_t)((wm + 16 * i + a_row_l) * LDS_PAD
                                          + ks + a_colb) * 2;
                LDSM4(ah[i], AhiB + off);
                LDSM4(al[i], AloB + off);
            }
#pragma unroll
            for (int jp = 0; jp < 2; jp++) {
                uint32_t off = (uint32_t)((wn + 16 * jp + b_row_l) * LDS_PAD
                                          + ks + b_colb) * 2;
                uint32_t q[4];
                LDSM4(q, BhiB + off);
                bh[2*jp][0] = q[0]; bh[2*jp][1] = q[1];
                bh[2*jp+1][0] = q[2]; bh[2*jp+1][1] = q[3];
                LDSM4(q, BloB + off);
                bl[2*jp][0] = q[0]; bl[2*jp][1] = q[1];
                bl[2*jp+1][0] = q[2]; bl[2*jp+1][1] = q[3];
            }
#pragma unroll
            for (int i = 0; i < 4; i++)
#pragma unroll
                for (int j = 0; j < 4; j++) {
                    MMA16816(d[i][j], ah[i], bh[j]);
                    MMA16816(d[i][j], ah[i], bl[j]);
                    MMA16816(d[i][j], al[i], bh[j]);
                }
        }
        __syncthreads();
    }

    // ---- epilogue: C frag -> gmem ----
    const int trow = lane >> 2, tcol = (lane & 3) * 2;
#pragma unroll
    for (int i = 0; i < 4; i++)
#pragma unroll
        for (int j = 0; j < 4; j++) {
            float* p = C + (size_t)(m0 + wm + 16 * i + trow) * N
                         + (n0 + wn + 8 * j + tcol);
            p[0] = d[i][j][0]; p[1] = d[i][j][1];
            float* p2 = p + (size_t)8 * N;
            p2[0] = d[i][j][2]; p2[1] = d[i][j][3];
        }
}

// ============================================================================
// RoPE on a head-block inside packed qkv (row stride = rowstr).
// ============================================================================
__global__ void rope_kernel(float* __restrict__ x, const float* __restrict__ cosT,
                            const float* __restrict__ sinT, int nheads, int rowstr)
{
    int idx = blockIdx.x * blockDim.x + threadIdx.x;
    int total = SEQ * nheads * 64;
    if (idx >= total) return;
    int d = idx & 63;
    int h = (idx >> 6) % nheads;
    int s = idx / (nheads << 6);
    float c  = cosT[s * HDIM + d];
    float sn = sinT[s * HDIM + d];
    float* p = x + (size_t)s * rowstr + h * HDIM;
    float x1 = p[d], x2 = p[d + 64];
    p[d]      = fmaf(x1, c, -x2 * sn);
    p[d + 64] = fmaf(x2, c,  x1 * sn);
}

// ============================================================================
// Causal flash attention, fp32 online softmax (FFMA).
// Q/K/V read from packed qkv (row stride 3072); O written at stride 2048.
// ============================================================================
#define QS_STRIDE  132
#define PS_STRIDE  68
#define FLASH_SMEM ((64 * 132 + 64 * 132 + 64 * 128 + 64 * 68) * 4)

__global__ __launch_bounds__(256) void flash_kernel(
    const float* __restrict__ Qg, const float* __restrict__ Kg,
    const float* __restrict__ Vg, float* __restrict__ Og)
{
    extern __shared__ float sm[];
    float* Qs = sm;                    // [64][132]
    float* Ks = sm + 64 * QS_STRIDE;   // [64][132]
    float* Vs = Ks + 64 * QS_STRIDE;   // [64][128]
    float* Ps = Vs + 64 * 128;         // [64][68]

    const int qt    = (int)gridDim.x - 1 - (int)blockIdx.x;
    const int h     = blockIdx.y;
    const int kvh   = h >> 2;
    const int tid   = threadIdx.x;
    const int ty    = tid >> 4;
    const int tx    = tid & 15;
    const int qbase = qt << 6;
    const float scale = 0.08838834764831845f;

    {
        const float* src = Qg + (size_t)qbase * QKV_STR + h * HDIM;
#pragma unroll
        for (int t = 0; t < 8; t++) {
            int idx = tid + t * 256;
            int r = idx >> 5;
            int c4 = (idx & 31) << 2;
            *(float4*)&Qs[r * QS_STRIDE + c4] =
                *(const float4*)(src + (size_t)r * QKV_STR + c4);
        }
    }

    float m_run[4], l_run[4], oacc[4][8];
#pragma unroll
    for (int i = 0; i < 4; i++) {
        m_run[i] = -1e30f; l_run[i] = 0.f;
#pragma unroll
        for (int c = 0; c < 8; c++) oacc[i][c] = 0.f;
    }

    for (int kt = 0; kt <= qt; kt++) {
        __syncthreads();
        {
            const float* ksrc = Kg + (size_t)(kt << 6) * QKV_STR + kvh * HDIM;
            const float* vsrc = Vg + (size_t)(kt << 6) * QKV_STR + kvh * HDIM;
#pragma unroll
            for (int t = 0; t < 8; t++) {
                int idx = tid + t * 256;
                int r = idx >> 5;
                int c4 = (idx & 31) << 2;
                *(float4*)&Ks[r * QS_STRIDE + c4] =
                    *(const float4*)(ksrc + (size_t)r * QKV_STR + c4);
                *(float4*)&Vs[r * 128 + c4] =
                    *(const float4*)(vsrc + (size_t)r * QKV_STR + c4);
            }
        }
        __syncthreads();

        float acc[4][4];
#pragma unroll
        for (int i = 0; i < 4; i++)
#pragma unroll
            for (int j = 0; j < 4; j++) acc[i][j] = 0.f;

        for (int kk = 0; kk < 128; kk += 4) {
            float4 qf[4], kf[4];
#pragma unroll
            for (int i = 0; i < 4; i++)
                qf[i] = *(const float4*)&Qs[(ty + 16 * i) * QS_STRIDE + kk];
#pragma unroll
            for (int j = 0; j < 4; j++)
                kf[j] = *(const float4*)&Ks[(tx + 16 * j) * QS_STRIDE + kk];
#pragma unroll
            for (int i = 0; i < 4; i++)
#pragma unroll
                for (int j = 0; j < 4; j++) {
                    acc[i][j] = fmaf(qf[i].x, kf[j].x, acc[i][j]);
                    acc[i][j] = fmaf(qf[i].y, kf[j].y, acc[i][j]);
                    acc[i][j] = fmaf(qf[i].z, kf[j].z, acc[i][j]);
                    acc[i][j] = fmaf(qf[i].w, kf[j].w, acc[i][j]);
                }
        }

        const int kbase = kt << 6;
#pragma unroll
        for (int i = 0; i < 4; i++) {
            int row = qbase + ty + 16 * i;
            float mt = -1e30f;
#pragma unroll
            for (int j = 0; j < 4; j++) {
                int col = kbase + tx + 16 * j;
                float sc = acc[i][j] * scale;
                if (col > row) sc = -1e30f;
                acc[i][j] = sc;
                mt = fmaxf(mt, sc);
            }
#pragma unroll
            for (int o = 8; o >= 1; o >>= 1)
                mt = fmaxf(mt, __shfl_xor_sync(0xffffffffu, mt, o));
            float mn = fmaxf(m_run[i], mt);
            float alpha = __expf(m_run[i] - mn);
            m_run[i] = mn;
            float rs = 0.f;
#pragma unroll
            for (int j = 0; j < 4; j++) {
                float p = __expf(acc[i][j] - mn);
                rs += p;
                Ps[(ty + 16 * i) * PS_STRIDE + tx + 16 * j] = p;
            }
#pragma unroll
            for (int o = 8; o >= 1; o >>= 1)
                rs += __shfl_xor_sync(0xffffffffu, rs, o);
            l_run[i] = l_run[i] * alpha + rs;
#pragma unroll
            for (int c = 0; c < 8; c++) oacc[i][c] *= alpha;
        }
        __syncthreads();

        for (int kk = 0; kk < 64; kk += 4) {
            float4 pf[4];
#pragma unroll
            for (int i = 0; i < 4; i++)
                pf[i] = *(const float4*)&Ps[(ty + 16 * i) * PS_STRIDE + kk];
            float pa[4][4];
#pragma unroll
            for (int i = 0; i < 4; i++) {
                pa[i][0] = pf[i].x; pa[i][1] = pf[i].y;
                pa[i][2] = pf[i].z; pa[i][3] = pf[i].w;
            }
#pragma unroll
            for (int u = 0; u < 4; u++) {
                float4 v0 = *(const float4*)&Vs[(kk + u) * 128 + (tx << 3)];
                float4 v1 = *(const float4*)&Vs[(kk + u) * 128 + (tx << 3) + 4];
#pragma unroll
                for (int i = 0; i < 4; i++) {
                    float p = pa[i][u];
                    oacc[i][0] = fmaf(p, v0.x, oacc[i][0]);
                    oacc[i][1] = fmaf(p, v0.y, oacc[i][1]);
                    oacc[i][2] = fmaf(p, v0.z, oacc[i][2]);
                    oacc[i][3] = fmaf(p, v0.w, oacc[i][3]);
                    oacc[i][4] = fmaf(p, v1.x, oacc[i][4]);
                    oacc[i][5] = fmaf(p, v1.y, oacc[i][5]);
                    oacc[i][6] = fmaf(p, v1.z, oacc[i][6]);
                    oacc[i][7] = fmaf(p, v1.w, oacc[i][7]);
                }
            }
        }
    }

#pragma unroll
    for (int i = 0; i < 4; i++) {
        float inv = 1.f / l_run[i];
        int row = qbase + ty + 16 * i;
        float* dst = Og + (size_t)row * QW + h * HDIM + (tx << 3);
        *(float4*)(dst)     = make_float4(oacc[i][0] * inv, oacc[i][1] * inv,
                                          oacc[i][2] * inv, oacc[i][3] * inv);
        *(float4*)(dst + 4) = make_float4(oacc[i][4] * inv, oacc[i][5] * inv,
                                          oacc[i][6] * inv, oacc[i][7] * inv);
    }
}

// ============================================================================
// Launch: split -> QKV GEMM (mma.sync) -> RoPE -> flash -> split -> O GEMM.
// Inputs: hidden, cos, sin, attention_mask(unused; causal analytic), wq,wk,wv,wo.
// ============================================================================
extern "C" void kernel_launch(void* const* d_in, const int* in_sizes, int n_in,
                              void* d_out, int out_size)
{
    const float* hidden = (const float*)d_in[0];
    const float* cosT   = (const float*)d_in[1];
    const float* sinT   = (const float*)d_in[2];
    const float* wq     = (const float*)d_in[4];
    const float* wk     = (const float*)d_in[5];
    const float* wv     = (const float*)d_in[6];
    const float* wo     = (const float*)d_in[7];
    float* out = (float*)d_out;

    float *qkv, *attn;
    __nv_bfloat16 *h_hi, *h_lo, *w_hi, *w_lo, *wo_hi, *wo_lo, *a_hi, *a_lo;
    cudaGetSymbolAddress((void**)&qkv,   g_qkv);
    cudaGetSymbolAddress((void**)&attn,  g_attn);
    cudaGetSymbolAddress((void**)&h_hi,  g_h_hi);
    cudaGetSymbolAddress((void**)&h_lo,  g_h_lo);
    cudaGetSymbolAddress((void**)&w_hi,  g_w_hi);
    cudaGetSymbolAddress((void**)&w_lo,  g_w_lo);
    cudaGetSymbolAddress((void**)&wo_hi, g_wo_hi);
    cudaGetSymbolAddress((void**)&wo_lo, g_wo_lo);
    cudaGetSymbolAddress((void**)&a_hi,  g_a_hi);
    cudaGetSymbolAddress((void**)&a_lo,  g_a_lo);

    cudaFuncSetAttribute(gemm_bf16x3,
                         cudaFuncAttributeMaxDynamicSharedMemorySize, GEMM_SMEM);
    cudaFuncSetAttribute(flash_kernel,
                         cudaFuncAttributeMaxDynamicSharedMemorySize, FLASH_SMEM);

#define SPLIT(src, dhi, dlo, n) \
    split_kernel<<<((n) / 4 + 255) / 256, 256>>>(src, dhi, dlo, n)

    SPLIT(hidden, h_hi, h_lo, SEQ * DM);
    SPLIT(wq, w_hi,                         w_lo,                         QW  * DM);
    SPLIT(wk, w_hi + (size_t)QW * DM,       w_lo + (size_t)QW * DM,       KWW * DM);
    SPLIT(wv, w_hi + (size_t)(QW+KWW) * DM, w_lo + (size_t)(QW+KWW) * DM, KWW * DM);
    SPLIT(wo, wo_hi, wo_lo, DM * QW);

    gemm_bf16x3<<<dim3(QKVW / 128, SEQ / 128), 256, GEMM_SMEM>>>(
        h_hi, h_lo, w_hi, w_lo, qkv, QKVW, DM);

    rope_kernel<<<(SEQ * NH  * 64 + 255) / 256, 256>>>(qkv,      cosT, sinT, NH,  QKV_STR);
    rope_kernel<<<(SEQ * NKV * 64 + 255) / 256, 256>>>(qkv + QW, cosT, sinT, NKV, QKV_STR);

    flash_kernel<<<dim3(SEQ / 64, NH), 256, FLASH_SMEM>>>(
        qkv, qkv + QW, qkv + QW + KWW, attn);

    SPLIT(attn, a_hi, a_lo, SEQ * QW);

    gemm_bf16x3<<<dim3(DM / 128, SEQ / 128), 256, GEMM_SMEM>>>(
        a_hi, a_lo, wo_hi, wo_lo, out, DM, DM);
}

// round 4
// speedup vs baseline: 3.0101x; 2.0561x over previous
#include <cuda_runtime.h>
#include <cuda_bf16.h>
#include <cstdint>
#include <math.h>

#define SEQ   4096
#define DM    2048
#define NH    16
#define NKV   4
#define HDIM  128
#define QW    (NH * HDIM)    /* 2048 */
#define KWW   (NKV * HDIM)   /* 512  */
#define QKVW  (QW + 2 * KWW) /* 3072 */

// ---------------- scratch (device globals; no allocations allowed) ----------
__device__ float g_qkv[SEQ * QKVW];          // fp32 packed [Q|K|V] from QKV GEMM
__device__ __nv_bfloat16 g_h_hi[SEQ * DM],  g_h_lo[SEQ * DM];
__device__ __nv_bfloat16 g_w_hi[QKVW * DM], g_w_lo[QKVW * DM];
__device__ __nv_bfloat16 g_wo_hi[DM * QW],  g_wo_lo[DM * QW];
__device__ __nv_bfloat16 g_q_hi[SEQ * QW],  g_q_lo[SEQ * QW];
__device__ __nv_bfloat16 g_k_hi[SEQ * KWW], g_k_lo[SEQ * KWW];
__device__ __nv_bfloat16 g_v_hi[SEQ * KWW], g_v_lo[SEQ * KWW];
__device__ __nv_bfloat16 g_a_hi[SEQ * QW],  g_a_lo[SEQ * QW];

// ---------------- helpers -----------------------------------------------------
__device__ __forceinline__ uint32_t smem_u32(const void* p) {
    uint32_t a;
    asm("{ .reg .u64 t; cvta.to.shared.u64 t, %1; cvt.u32.u64 %0, t; }"
        : "=r"(a) : "l"(p));
    return a;
}

__device__ __forceinline__ void cp16(uint32_t dst, const void* src) {
    asm volatile("cp.async.cg.shared.global [%0], [%1], 16;" :: "r"(dst), "l"(src));
}
#define CP_COMMIT() asm volatile("cp.async.commit_group;" ::: "memory")
#define CP_WAIT(n)  asm volatile("cp.async.wait_group %0;" :: "n"(n) : "memory")

#define LDSM4(r, addr)                                                        \
    asm volatile("ldmatrix.sync.aligned.m8n8.x4.shared.b16 {%0,%1,%2,%3}, [%4];" \
        : "=r"((r)[0]), "=r"((r)[1]), "=r"((r)[2]), "=r"((r)[3]) : "r"(addr))

#define LDSM4T(r, addr)                                                       \
    asm volatile("ldmatrix.sync.aligned.m8n8.x4.trans.shared.b16 {%0,%1,%2,%3}, [%4];" \
        : "=r"((r)[0]), "=r"((r)[1]), "=r"((r)[2]), "=r"((r)[3]) : "r"(addr))

#define MMA16816(d, a, b)                                                     \
    asm volatile("mma.sync.aligned.m16n8k16.row.col.f32.bf16.bf16.f32 "       \
        "{%0,%1,%2,%3}, {%4,%5,%6,%7}, {%8,%9}, {%0,%1,%2,%3};"               \
        : "+f"((d)[0]), "+f"((d)[1]), "+f"((d)[2]), "+f"((d)[3])              \
        : "r"((a)[0]), "r"((a)[1]), "r"((a)[2]), "r"((a)[3]),                 \
          "r"((b)[0]), "r"((b)[1]))

// split a pair of floats into bf16x2 hi and bf16x2 lo (residual)
__device__ __forceinline__ void bsplit2(float x, float y,
                                        uint32_t& hip, uint32_t& lop) {
    __nv_bfloat16 hx = __float2bfloat16(x), hy = __float2bfloat16(y);
    float rx = x - __bfloat162float(hx), ry = y - __bfloat162float(hy);
    __nv_bfloat162 hp; hp.x = hx; hp.y = hy;
    __nv_bfloat162 lp = __floats2bfloat162_rn(rx, ry);
    hip = *reinterpret_cast<uint32_t*>(&hp);
    lop = *reinterpret_cast<uint32_t*>(&lp);
}

// ============================================================================
// fp32 -> (bf16 hi, bf16 lo). n divisible by 4. (inputs: hidden, weights)
// ============================================================================
__global__ void split_kernel(const float* __restrict__ x,
                             __nv_bfloat16* __restrict__ hi,
                             __nv_bfloat16* __restrict__ lo, int n)
{
    int i = (blockIdx.x * blockDim.x + threadIdx.x) * 4;
    if (i >= n) return;
    float4 v = *(const float4*)(x + i);
    uint32_t h0, l0, h1, l1;
    bsplit2(v.x, v.y, h0, l0);
    bsplit2(v.z, v.w, h1, l1);
    *(uint32_t*)(hi + i)     = h0; *(uint32_t*)(hi + i + 2) = h1;
    *(uint32_t*)(lo + i)     = l0; *(uint32_t*)(lo + i + 2) = l1;
}

// ============================================================================
// mma.sync bf16 NT GEMM, 3-term split (validated round 3).
// ============================================================================
#define BK          32
#define LDS_PAD     40
#define TILE_BYTES  (128 * LDS_PAD * 2)
#define STAGE_BYTES (4 * TILE_BYTES)
#define GEMM_SMEM   (2 * STAGE_BYTES)

__global__ __launch_bounds__(256, 1) void gemm_bf16x3(
    const __nv_bfloat16* __restrict__ Ahi, const __nv_bfloat16* __restrict__ Alo,
    const __nv_bfloat16* __restrict__ Bhi, const __nv_bfloat16* __restrict__ Blo,
    float* __restrict__ C, int N, int K)
{
    extern __shared__ char smem[];
    const uint32_t sb = smem_u32(smem);
    const int tid  = threadIdx.x;
    const int wid  = tid >> 5, lane = tid & 31;
    const int m0   = blockIdx.y * 128, n0 = blockIdx.x * 128;
    const int wm   = (wid & 1) * 64;
    const int wn   = (wid >> 1) * 32;

    const __nv_bfloat16* srcs[4] = {
        Ahi + (size_t)m0 * K, Alo + (size_t)m0 * K,
        Bhi + (size_t)n0 * K, Blo + (size_t)n0 * K };

    const int a_row_l = lane & 15;
    const int a_colb  = ((lane >> 4) & 1) << 3;
    const int b_row_l = (lane & 7) + (((lane >> 4) & 1) << 3);
    const int b_colb  = ((lane >> 3) & 1) << 3;

    float d[4][4][4];
#pragma unroll
    for (int i = 0; i < 4; i++)
#pragma unroll
        for (int j = 0; j < 4; j++)
#pragma unroll
            for (int q = 0; q < 4; q++) d[i][j][q] = 0.f;

    const int nk = K / BK;

#define LOAD_STAGE(s, k0) do {                                                \
    uint32_t stb = sb + (uint32_t)(s) * STAGE_BYTES;                          \
    _Pragma("unroll")                                                         \
    for (int t = 0; t < 4; t++) {                                             \
        const __nv_bfloat16* src = srcs[t] + (k0);                            \
        uint32_t dstb = stb + (uint32_t)t * TILE_BYTES;                       \
        _Pragma("unroll")                                                     \
        for (int it = 0; it < 2; it++) {                                      \
            int idx = tid + it * 256;                                         \
            int r = idx >> 2, c = idx & 3;                                    \
            cp16(dstb + (uint32_t)(r * LDS_PAD + c * 8) * 2,                  \
                 src + (size_t)r * K + c * 8);                                \
        }                                                                     \
    }                                                                         \
    CP_COMMIT();                                                              \
} while (0)

    LOAD_STAGE(0, 0);

    for (int kt = 0; kt < nk; kt++) {
        if (kt + 1 < nk) { LOAD_STAGE((kt + 1) & 1, (kt + 1) * BK); CP_WAIT(1); }
        else             { CP_WAIT(0); }
        __syncthreads();

        const uint32_t stb  = sb + (uint32_t)(kt & 1) * STAGE_BYTES;
        const uint32_t AhiB = stb;
        const uint32_t AloB = stb + TILE_BYTES;
        const uint32_t BhiB = stb + 2 * TILE_BYTES;
        const uint32_t BloB = stb + 3 * TILE_BYTES;

#pragma unroll
        for (int ks = 0; ks < BK; ks += 16) {
            uint32_t ah[4][4], al[4][4], bh[4][2], bl[4][2];
#pragma unroll
            for (int i = 0; i < 4; i++) {
                uint32_t off = (uint32_t)((wm + 16 * i + a_row_l) * LDS_PAD
                                          + ks + a_colb) * 2;
                LDSM4(ah[i], AhiB + off);
                LDSM4(al[i], AloB + off);
            }
#pragma unroll
            for (int jp = 0; jp < 2; jp++) {
                uint32_t off = (uint32_t)((wn + 16 * jp + b_row_l) * LDS_PAD
                                          + ks + b_colb) * 2;
                uint32_t q[4];
                LDSM4(q, BhiB + off);
                bh[2*jp][0] = q[0]; bh[2*jp][1] = q[1];
                bh[2*jp+1][0] = q[2]; bh[2*jp+1][1] = q[3];
                LDSM4(q, BloB + off);
                bl[2*jp][0] = q[0]; bl[2*jp][1] = q[1];
                bl[2*jp+1][0] = q[2]; bl[2*jp+1][1] = q[3];
            }
#pragma unroll
            for (int i = 0; i < 4; i++)
#pragma unroll
                for (int j = 0; j < 4; j++) {
                    MMA16816(d[i][j], ah[i], bh[j]);
                    MMA16816(d[i][j], ah[i], bl[j]);
                    MMA16816(d[i][j], al[i], bh[j]);
                }
        }
        __syncthreads();
    }

    const int trow = lane >> 2, tcol = (lane & 3) * 2;
#pragma unroll
    for (int i = 0; i < 4; i++)
#pragma unroll
        for (int j = 0; j < 4; j++) {
            float* p = C + (size_t)(m0 + wm + 16 * i + trow) * N
                         + (n0 + wn + 8 * j + tcol);
            p[0] = d[i][j][0]; p[1] = d[i][j][1];
            float* p2 = p + (size_t)8 * N;
            p2[0] = d[i][j][2]; p2[1] = d[i][j][3];
        }
}

// ============================================================================
// Fused RoPE + bf16 split for Q and K heads of packed qkv.
// One thread per (seq, head, d<64) rotation pair; heads 0..15 -> Q, 16..19 -> K.
// ============================================================================
__global__ void rope_split_qk(const float* __restrict__ qkv,
                              const float* __restrict__ cosT,
                              const float* __restrict__ sinT,
                              __nv_bfloat16* __restrict__ qhi, __nv_bfloat16* __restrict__ qlo,
                              __nv_bfloat16* __restrict__ khi, __nv_bfloat16* __restrict__ klo)
{
    int idx = blockIdx.x * blockDim.x + threadIdx.x;
    if (idx >= SEQ * 20 * 64) return;
    int d  = idx & 63;
    int hh = (idx >> 6) % 20;
    int s  = idx / (20 * 64);
    const float* p = qkv + (size_t)s * QKVW + hh * HDIM;
    float x1 = p[d], x2 = p[d + 64];
    float c  = cosT[s * HDIM + d];
    float sn = sinT[s * HDIM + d];
    float y1 = fmaf(x1, c, -x2 * sn);
    float y2 = fmaf(x2, c,  x1 * sn);
    __nv_bfloat16 h1 = __float2bfloat16(y1), h2 = __float2bfloat16(y2);
    __nv_bfloat16 l1 = __float2bfloat16(y1 - __bfloat162float(h1));
    __nv_bfloat16 l2 = __float2bfloat16(y2 - __bfloat162float(h2));
    if (hh < NH) {
        size_t o = (size_t)s * QW + hh * HDIM;
        qhi[o + d] = h1; qhi[o + d + 64] = h2;
        qlo[o + d] = l1; qlo[o + d + 64] = l2;
    } else {
        size_t o = (size_t)s * KWW + (hh - NH) * HDIM;
        khi[o + d] = h1; khi[o + d + 64] = h2;
        klo[o + d] = l1; klo[o + d + 64] = l2;
    }
}

// V part of qkv -> bf16 hi/lo (no rope)
__global__ void split_v(const float* __restrict__ qkv,
                        __nv_bfloat16* __restrict__ vhi,
                        __nv_bfloat16* __restrict__ vlo)
{
    int idx = blockIdx.x * blockDim.x + threadIdx.x;
    if (idx >= SEQ * KWW) return;
    int c = idx & (KWW - 1);
    int s = idx >> 9;
    float x = qkv[(size_t)s * QKVW + QW + KWW + c];
    __nv_bfloat16 h = __float2bfloat16(x);
    vhi[(size_t)s * KWW + c] = h;
    vlo[(size_t)s * KWW + c] = __float2bfloat16(x - __bfloat162float(h));
}

// ============================================================================
// Tensor-core causal flash attention (bf16 3-term split, fp32 softmax).
// CTA = 128 q-rows x 1 head. 8 warps x 16 rows. K/V tiles 64 rows,
// double-buffered cp.async. Outputs bf16 hi/lo directly for the O-proj GEMM.
// ============================================================================
#define BQ      128
#define BKV     64
#define FL_STR  136
#define FL_QT   (BQ * FL_STR * 2)        /* 34816 */
#define FL_KT   (BKV * FL_STR * 2)       /* 17408 */
#define FL_STG  (4 * FL_KT)              /* 69632 */
#define FLASH_SMEM (2 * FL_QT + 2 * FL_STG)  /* 208896 */

__global__ __launch_bounds__(256, 1) void flash_mma(
    const __nv_bfloat16* __restrict__ Qhi, const __nv_bfloat16* __restrict__ Qlo,
    const __nv_bfloat16* __restrict__ Khi, const __nv_bfloat16* __restrict__ Klo,
    const __nv_bfloat16* __restrict__ Vhi, const __nv_bfloat16* __restrict__ Vlo,
    __nv_bfloat16* __restrict__ Ohi, __nv_bfloat16* __restrict__ Olo)
{
    extern __shared__ char smem[];
    const uint32_t sbm = smem_u32(smem);
    const uint32_t QHI = sbm, QLO = sbm + FL_QT;
    const uint32_t ST0 = sbm + 2 * FL_QT;

    const int qt  = (int)gridDim.x - 1 - (int)blockIdx.x;  // big tiles first
    const int h   = blockIdx.y;
    const int kvh = h >> 2;
    const int tid = threadIdx.x, wid = tid >> 5, lane = tid & 31;
    const int qbase = qt * BQ;
    const int wm  = wid * 16;
    const int nkt = 2 * qt + 2;
    const float scale = 0.08838834764831845f;

    const int a_row = lane & 15;
    const int a_cb  = ((lane >> 4) & 1) << 3;
    const int b_row = (lane & 7) + (((lane >> 4) & 1) << 3);
    const int b_cb  = ((lane >> 3) & 1) << 3;
    const int v_row = (lane & 7) + (((lane >> 3) & 1) << 3);
    const int v_cb  = ((lane >> 4) & 1) << 3;
    const int r0    = lane >> 2;
    const int colq  = (lane & 3) * 2;

    // ---- Q tile load (hi+lo) ----
    {
        const size_t qoff = (size_t)qbase * QW + h * HDIM;
#pragma unroll
        for (int it = 0; it < 8; it++) {
            int idx = tid + it * 256;
            int r = idx >> 4, c = idx & 15;
            uint32_t d = (uint32_t)(r * FL_STR + c * 8) * 2;
            cp16(QHI + d, Qhi + qoff + (size_t)r * QW + c * 8);
            cp16(QLO + d, Qlo + qoff + (size_t)r * QW + c * 8);
        }
        CP_COMMIT();
    }

#define FL_LOAD(s, kb) do {                                                   \
    uint32_t stb_ = ST0 + (uint32_t)(s) * FL_STG;                             \
    const size_t ko_ = (size_t)(kb) * KWW + kvh * HDIM;                       \
    _Pragma("unroll")                                                         \
    for (int it = 0; it < 4; it++) {                                          \
        int idx = tid + it * 256;                                             \
        int r = idx >> 4, c = idx & 15;                                       \
        uint32_t d_ = (uint32_t)(r * FL_STR + c * 8) * 2;                     \
        const size_t so_ = ko_ + (size_t)r * KWW + c * 8;                     \
        cp16(stb_ + 0 * FL_KT + d_, Khi + so_);                               \
        cp16(stb_ + 1 * FL_KT + d_, Klo + so_);                               \
        cp16(stb_ + 2 * FL_KT + d_, Vhi + so_);                               \
        cp16(stb_ + 3 * FL_KT + d_, Vlo + so_);                               \
    }                                                                         \
    CP_COMMIT();                                                              \
} while (0)

    FL_LOAD(0, 0);

    float m0 = -1e30f, m1 = -1e30f, l0 = 0.f, l1 = 0.f;
    float o[16][4];
#pragma unroll
    for (int j = 0; j < 16; j++)
#pragma unroll
        for (int q = 0; q < 4; q++) o[j][q] = 0.f;

    for (int kt = 0; kt < nkt; kt++) {
        if (kt + 1 < nkt) { FL_LOAD((kt + 1) & 1, (kt + 1) * BKV); CP_WAIT(1); }
        else              { CP_WAIT(0); }
        __syncthreads();

        const uint32_t stb = ST0 + (uint32_t)(kt & 1) * FL_STG;
        const uint32_t KH = stb, KL = stb + FL_KT;
        const uint32_t VH = stb + 2 * FL_KT, VL = stb + 3 * FL_KT;

        // ---- S = Q K^T (3-term) ----
        float s[8][4];
#pragma unroll
        for (int j = 0; j < 8; j++)
#pragma unroll
            for (int q = 0; q < 4; q++) s[j][q] = 0.f;

#pragma unroll
        for (int ks = 0; ks < 8; ks++) {
            uint32_t ah[4], al[4];
            uint32_t qoff = (uint32_t)((wm + a_row) * FL_STR + ks * 16 + a_cb) * 2;
            LDSM4(ah, QHI + qoff);
            LDSM4(al, QLO + qoff);
#pragma unroll
            for (int jp = 0; jp < 4; jp++) {
                uint32_t bh[4], bl[4];
                uint32_t koff = (uint32_t)((jp * 16 + b_row) * FL_STR + ks * 16 + b_cb) * 2;
                LDSM4(bh, KH + koff);
                LDSM4(bl, KL + koff);
                MMA16816(s[2*jp],   ah, bh);
                MMA16816(s[2*jp],   al, bh);
                MMA16816(s[2*jp],   ah, bl);
                MMA16816(s[2*jp+1], ah, bh + 2);
                MMA16816(s[2*jp+1], al, bh + 2);
                MMA16816(s[2*jp+1], ah, bl + 2);
            }
        }

        // ---- softmax (scale, causal mask, online update) ----
        const int kbase = kt * BKV;
        if (kbase + BKV - 1 > qbase + wm) {   // warp-uniform: diagonal tile
            const int row0g = qbase + wm + r0, row1g = row0g + 8;
#pragma unroll
            for (int j = 0; j < 8; j++) {
                int c0 = kbase + j * 8 + colq, c1 = c0 + 1;
                s[j][0] = (c0 <= row0g) ? s[j][0] * scale : -1e30f;
                s[j][1] = (c1 <= row0g) ? s[j][1] * scale : -1e30f;
                s[j][2] = (c0 <= row1g) ? s[j][2] * scale : -1e30f;
                s[j][3] = (c1 <= row1g) ? s[j][3] * scale : -1e30f;
            }
        } else {
#pragma unroll
            for (int j = 0; j < 8; j++) {
                s[j][0] *= scale; s[j][1] *= scale;
                s[j][2] *= scale; s[j][3] *= scale;
            }
        }

        float rmax0 = -1e30f, rmax1 = -1e30f;
#pragma unroll
        for (int j = 0; j < 8; j++) {
            rmax0 = fmaxf(rmax0, fmaxf(s[j][0], s[j][1]));
            rmax1 = fmaxf(rmax1, fmaxf(s[j][2], s[j][3]));
        }
        rmax0 = fmaxf(rmax0, __shfl_xor_sync(0xffffffffu, rmax0, 1));
        rmax0 = fmaxf(rmax0, __shfl_xor_sync(0xffffffffu, rmax0, 2));
        rmax1 = fmaxf(rmax1, __shfl_xor_sync(0xffffffffu, rmax1, 1));
        rmax1 = fmaxf(rmax1, __shfl_xor_sync(0xffffffffu, rmax1, 2));

        float mn0 = fmaxf(m0, rmax0), mn1 = fmaxf(m1, rmax1);
        float al0 = __expf(m0 - mn0), al1 = __expf(m1 - mn1);
        m0 = mn0; m1 = mn1;

        float rs0 = 0.f, rs1 = 0.f;
#pragma unroll
        for (int j = 0; j < 8; j++) {
            s[j][0] = __expf(s[j][0] - mn0); rs0 += s[j][0];
            s[j][1] = __expf(s[j][1] - mn0); rs0 += s[j][1];
            s[j][2] = __expf(s[j][2] - mn1); rs1 += s[j][2];
            s[j][3] = __expf(s[j][3] - mn1); rs1 += s[j][3];
        }
        rs0 += __shfl_xor_sync(0xffffffffu, rs0, 1);
        rs0 += __shfl_xor_sync(0xffffffffu, rs0, 2);
        rs1 += __shfl_xor_sync(0xffffffffu, rs1, 1);
        rs1 += __shfl_xor_sync(0xffffffffu, rs1, 2);
        l0 = l0 * al0 + rs0;
        l1 = l1 * al1 + rs1;

#pragma unroll
        for (int j = 0; j < 16; j++) {
            o[j][0] *= al0; o[j][1] *= al0;
            o[j][2] *= al1; o[j][3] *= al1;
        }

        // ---- O += P V (P split in registers, 3-term) ----
#pragma unroll
        for (int t = 0; t < 4; t++) {
            uint32_t ph[4], pl[4];
            bsplit2(s[2*t][0],   s[2*t][1],   ph[0], pl[0]);
            bsplit2(s[2*t][2],   s[2*t][3],   ph[1], pl[1]);
            bsplit2(s[2*t+1][0], s[2*t+1][1], ph[2], pl[2]);
            bsplit2(s[2*t+1][2], s[2*t+1][3], ph[3], pl[3]);
#pragma unroll
            for (int jp = 0; jp < 8; jp++) {
                uint32_t vh[4], vl[4];
                uint32_t voff = (uint32_t)((t * 16 + v_row) * FL_STR
                                           + jp * 16 + v_cb) * 2;
                LDSM4T(vh, VH + voff);
                LDSM4T(vl, VL + voff);
                MMA16816(o[2*jp],   ph, vh);
                MMA16816(o[2*jp],   pl, vh);
                MMA16816(o[2*jp],   ph, vl);
                MMA16816(o[2*jp+1], ph, vh + 2);
                MMA16816(o[2*jp+1], pl, vh + 2);
                MMA16816(o[2*jp+1], ph, vl + 2);
            }
        }
        __syncthreads();   // all warps done with stage before it is reloaded
    }

    // ---- epilogue: normalize, bf16-split, store ----
    const float inv0 = 1.f / l0, inv1 = 1.f / l1;
    const int row0g = qbase + wm + r0;
    const size_t base0 = (size_t)row0g * QW + h * HDIM;
    const size_t base1 = base0 + (size_t)8 * QW;
#pragma unroll
    for (int j = 0; j < 16; j++) {
        int col = j * 8 + colq;
        uint32_t hp, lp;
        bsplit2(o[j][0] * inv0, o[j][1] * inv0, hp, lp);
        *(uint32_t*)(Ohi + base0 + col) = hp;
        *(uint32_t*)(Olo + base0 + col) = lp;
        bsplit2(o[j][2] * inv1, o[j][3] * inv1, hp, lp);
        *(uint32_t*)(Ohi + base1 + col) = hp;
        *(uint32_t*)(Olo + base1 + col) = lp;
    }
}

// ============================================================================
// Launch
// ============================================================================
extern "C" void kernel_launch(void* const* d_in, const int* in_sizes, int n_in,
                              void* d_out, int out_size)
{
    const float* hidden = (const float*)d_in[0];
    const float* cosT   = (const float*)d_in[1];
    const float* sinT   = (const float*)d_in[2];
    const float* wq     = (const float*)d_in[4];
    const float* wk     = (const float*)d_in[5];
    const float* wv     = (const float*)d_in[6];
    const float* wo     = (const float*)d_in[7];
    float* out = (float*)d_out;

    float* qkv;
    __nv_bfloat16 *h_hi, *h_lo, *w_hi, *w_lo, *wo_hi, *wo_lo;
    __nv_bfloat16 *q_hi, *q_lo, *k_hi, *k_lo, *v_hi, *v_lo, *a_hi, *a_lo;
    cudaGetSymbolAddress((void**)&qkv,   g_qkv);
    cudaGetSymbolAddress((void**)&h_hi,  g_h_hi);
    cudaGetSymbolAddress((void**)&h_lo,  g_h_lo);
    cudaGetSymbolAddress((void**)&w_hi,  g_w_hi);
    cudaGetSymbolAddress((void**)&w_lo,  g_w_lo);
    cudaGetSymbolAddress((void**)&wo_hi, g_wo_hi);
    cudaGetSymbolAddress((void**)&wo_lo, g_wo_lo);
    cudaGetSymbolAddress((void**)&q_hi,  g_q_hi);
    cudaGetSymbolAddress((void**)&q_lo,  g_q_lo);
    cudaGetSymbolAddress((void**)&k_hi,  g_k_hi);
    cudaGetSymbolAddress((void**)&k_lo,  g_k_lo);
    cudaGetSymbolAddress((void**)&v_hi,  g_v_hi);
    cudaGetSymbolAddress((void**)&v_lo,  g_v_lo);
    cudaGetSymbolAddress((void**)&a_hi,  g_a_hi);
    cudaGetSymbolAddress((void**)&a_lo,  g_a_lo);

    cudaFuncSetAttribute(gemm_bf16x3,
                         cudaFuncAttributeMaxDynamicSharedMemorySize, GEMM_SMEM);
    cudaFuncSetAttribute(flash_mma,
                         cudaFuncAttributeMaxDynamicSharedMemorySize, FLASH_SMEM);

#define SPLIT(src, dhi, dlo, n) \
    split_kernel<<<((n) / 4 + 255) / 256, 256>>>(src, dhi, dlo, n)

    SPLIT(hidden, h_hi, h_lo, SEQ * DM);
    SPLIT(wq, w_hi,                         w_lo,                         QW  * DM);
    SPLIT(wk, w_hi + (size_t)QW * DM,       w_lo + (size_t)QW * DM,       KWW * DM);
    SPLIT(wv, w_hi + (size_t)(QW+KWW) * DM, w_lo + (size_t)(QW+KWW) * DM, KWW * DM);
    SPLIT(wo, wo_hi, wo_lo, DM * QW);

    gemm_bf16x3<<<dim3(QKVW / 128, SEQ / 128), 256, GEMM_SMEM>>>(
        h_hi, h_lo, w_hi, w_lo, qkv, QKVW, DM);

    rope_split_qk<<<(SEQ * 20 * 64 + 255) / 256, 256>>>(
        qkv, cosT, sinT, q_hi, q_lo, k_hi, k_lo);
    split_v<<<(SEQ * KWW + 255) / 256, 256>>>(qkv, v_hi, v_lo);

    flash_mma<<<dim3(SEQ / BQ, NH), 256, FLASH_SMEM>>>(
        q_hi, q_lo, k_hi, k_lo, v_hi, v_lo, a_hi, a_lo);

    gemm_bf16x3<<<dim3(DM / 128, SEQ / 128), 256, GEMM_SMEM>>>(
        a_hi, a_lo, wo_hi, wo_lo, out, DM, DM);
}

// round 5
// speedup vs baseline: 3.2391x; 1.0761x over previous
#include <cuda_runtime.h>
#include <cuda_bf16.h>
#include <cstdint>
#include <math.h>

#define SEQ   4096
#define DM    2048
#define NH    16
#define NKV   4
#define HDIM  128
#define QW    (NH * HDIM)    /* 2048 */
#define KWW   (NKV * HDIM)   /* 512  */
#define QKVW  (QW + 2 * KWW) /* 3072 */

// ---------------- scratch (device globals; no allocations allowed) ----------
__device__ float g_qkv[SEQ * QKVW];          // fp32 packed [Q|K|V] from QKV GEMM
__device__ __nv_bfloat16 g_h_hi[SEQ * DM],  g_h_lo[SEQ * DM];
__device__ __nv_bfloat16 g_w_hi[QKVW * DM], g_w_lo[QKVW * DM];
__device__ __nv_bfloat16 g_wo_hi[DM * QW],  g_wo_lo[DM * QW];
__device__ __nv_bfloat16 g_q_hi[SEQ * QW],  g_q_lo[SEQ * QW];
__device__ __nv_bfloat16 g_k_hi[SEQ * KWW], g_k_lo[SEQ * KWW];
__device__ __nv_bfloat16 g_v_hi[SEQ * KWW], g_v_lo[SEQ * KWW];
__device__ __nv_bfloat16 g_a_hi[SEQ * QW],  g_a_lo[SEQ * QW];

// ---------------- helpers -----------------------------------------------------
__device__ __forceinline__ uint32_t smem_u32(const void* p) {
    uint32_t a;
    asm("{ .reg .u64 t; cvta.to.shared.u64 t, %1; cvt.u32.u64 %0, t; }"
        : "=r"(a) : "l"(p));
    return a;
}

__device__ __forceinline__ void cp16(uint32_t dst, const void* src) {
    asm volatile("cp.async.cg.shared.global [%0], [%1], 16;" :: "r"(dst), "l"(src));
}
#define CP_COMMIT() asm volatile("cp.async.commit_group;" ::: "memory")
#define CP_WAIT(n)  asm volatile("cp.async.wait_group %0;" :: "n"(n) : "memory")

#define LDSM4(r, addr)                                                        \
    asm volatile("ldmatrix.sync.aligned.m8n8.x4.shared.b16 {%0,%1,%2,%3}, [%4];" \
        : "=r"((r)[0]), "=r"((r)[1]), "=r"((r)[2]), "=r"((r)[3]) : "r"(addr))

#define LDSM4T(r, addr)                                                       \
    asm volatile("ldmatrix.sync.aligned.m8n8.x4.trans.shared.b16 {%0,%1,%2,%3}, [%4];" \
        : "=r"((r)[0]), "=r"((r)[1]), "=r"((r)[2]), "=r"((r)[3]) : "r"(addr))

#define MMA16816(d, a, b)                                                     \
    asm volatile("mma.sync.aligned.m16n8k16.row.col.f32.bf16.bf16.f32 "       \
        "{%0,%1,%2,%3}, {%4,%5,%6,%7}, {%8,%9}, {%0,%1,%2,%3};"               \
        : "+f"((d)[0]), "+f"((d)[1]), "+f"((d)[2]), "+f"((d)[3])              \
        : "r"((a)[0]), "r"((a)[1]), "r"((a)[2]), "r"((a)[3]),                 \
          "r"((b)[0]), "r"((b)[1]))

__device__ __forceinline__ void bsplit2(float x, float y,
                                        uint32_t& hip, uint32_t& lop) {
    __nv_bfloat16 hx = __float2bfloat16(x), hy = __float2bfloat16(y);
    float rx = x - __bfloat162float(hx), ry = y - __bfloat162float(hy);
    __nv_bfloat162 hp; hp.x = hx; hp.y = hy;
    __nv_bfloat162 lp = __floats2bfloat162_rn(rx, ry);
    hip = *reinterpret_cast<uint32_t*>(&hp);
    lop = *reinterpret_cast<uint32_t*>(&lp);
}

// ============================================================================
// fp32 -> (bf16 hi, bf16 lo). n divisible by 4.
// ============================================================================
__global__ void split_kernel(const float* __restrict__ x,
                             __nv_bfloat16* __restrict__ hi,
                             __nv_bfloat16* __restrict__ lo, int n)
{
    int i = (blockIdx.x * blockDim.x + threadIdx.x) * 4;
    if (i >= n) return;
    float4 v = *(const float4*)(x + i);
    uint32_t h0, l0, h1, l1;
    bsplit2(v.x, v.y, h0, l0);
    bsplit2(v.z, v.w, h1, l1);
    *(uint32_t*)(hi + i)     = h0; *(uint32_t*)(hi + i + 2) = h1;
    *(uint32_t*)(lo + i)     = l0; *(uint32_t*)(lo + i + 2) = l1;
}

// ============================================================================
// mma.sync bf16 NT GEMM, 3-term split. CTA tile 128(M)x256(N), BK=32,
// 8 warps as 2Mx4N (warp tile 64x64), 3-stage cp.async pipeline.
// ============================================================================
#define BK        32
#define LDS_PAD   40
#define A_TILE_B  (128 * LDS_PAD * 2)          /* 10240 */
#define B_TILE_B  (256 * LDS_PAD * 2)          /* 20480 */
#define STAGE_B   (2 * A_TILE_B + 2 * B_TILE_B) /* 61440 */
#define NSTAGE    3
#define GEMM_SMEM (NSTAGE * STAGE_B)            /* 184320 */

__global__ __launch_bounds__(256, 1) void gemm_bf16x3(
    const __nv_bfloat16* __restrict__ Ahi, const __nv_bfloat16* __restrict__ Alo,
    const __nv_bfloat16* __restrict__ Bhi, const __nv_bfloat16* __restrict__ Blo,
    float* __restrict__ C, int N, int K)
{
    extern __shared__ char smem[];
    const uint32_t sb = smem_u32(smem);
    const int tid  = threadIdx.x;
    const int wid  = tid >> 5, lane = tid & 31;
    const int m0   = blockIdx.y * 128, n0 = blockIdx.x * 256;
    const int wm   = (wid & 1) * 64;
    const int wn   = (wid >> 1) * 64;

    const __nv_bfloat16* a_hi = Ahi + (size_t)m0 * K;
    const __nv_bfloat16* a_lo = Alo + (size_t)m0 * K;
    const __nv_bfloat16* b_hi = Bhi + (size_t)n0 * K;
    const __nv_bfloat16* b_lo = Blo + (size_t)n0 * K;

    const int a_row_l = lane & 15;
    const int a_colb  = ((lane >> 4) & 1) << 3;
    const int b_row_l = (lane & 7) + (((lane >> 4) & 1) << 3);
    const int b_colb  = ((lane >> 3) & 1) << 3;

    float d[4][8][4];
#pragma unroll
    for (int i = 0; i < 4; i++)
#pragma unroll
        for (int j = 0; j < 8; j++)
#pragma unroll
            for (int q = 0; q < 4; q++) d[i][j][q] = 0.f;

    const int nk = K / BK;

#define LOAD_STAGE(s, k0) do {                                                \
    uint32_t stb = sb + (uint32_t)(s) * STAGE_B;                              \
    _Pragma("unroll")                                                         \
    for (int it = 0; it < 2; it++) {    /* A hi/lo: 128 rows x 4 chunks */    \
        int idx = tid + it * 256;                                             \
        int r = idx >> 2, c = idx & 3;                                        \
        uint32_t doff = (uint32_t)(r * LDS_PAD + c * 8) * 2;                  \
        size_t soff = (size_t)r * K + (k0) + c * 8;                           \
        cp16(stb + doff,            a_hi + soff);                             \
        cp16(stb + A_TILE_B + doff, a_lo + soff);                             \
    }                                                                         \
    _Pragma("unroll")                                                         \
    for (int it = 0; it < 4; it++) {    /* B hi/lo: 256 rows x 4 chunks */    \
        int idx = tid + it * 256;                                             \
        int r = idx >> 2, c = idx & 3;                                        \
        uint32_t doff = (uint32_t)(r * LDS_PAD + c * 8) * 2;                  \
        size_t soff = (size_t)r * K + (k0) + c * 8;                           \
        cp16(stb + 2 * A_TILE_B + doff,            b_hi + soff);              \
        cp16(stb + 2 * A_TILE_B + B_TILE_B + doff, b_lo + soff);              \
    }                                                                         \
    CP_COMMIT();                                                              \
} while (0)

    LOAD_STAGE(0, 0);
    LOAD_STAGE(1, BK);

    for (int kt = 0; kt < nk; kt++) {
        if (kt + 2 < nk)      { LOAD_STAGE((kt + 2) % NSTAGE, (kt + 2) * BK); CP_WAIT(2); }
        else if (kt + 1 < nk) { CP_WAIT(1); }
        else                  { CP_WAIT(0); }
        __syncthreads();

        const uint32_t stb  = sb + (uint32_t)(kt % NSTAGE) * STAGE_B;
        const uint32_t AhiB = stb;
        const uint32_t AloB = stb + A_TILE_B;
        const uint32_t BhiB = stb + 2 * A_TILE_B;
        const uint32_t BloB = stb + 2 * A_TILE_B + B_TILE_B;

#pragma unroll
        for (int ks = 0; ks < BK; ks += 16) {
            uint32_t ah[4][4], al[4][4];
#pragma unroll
            for (int i = 0; i < 4; i++) {
                uint32_t off = (uint32_t)((wm + 16 * i + a_row_l) * LDS_PAD
                                          + ks + a_colb) * 2;
                LDSM4(ah[i], AhiB + off);
                LDSM4(al[i], AloB + off);
            }
#pragma unroll
            for (int jp = 0; jp < 4; jp++) {
                uint32_t bh[4], bl[4];
                uint32_t off = (uint32_t)((wn + 16 * jp + b_row_l) * LDS_PAD
                                          + ks + b_colb) * 2;
                LDSM4(bh, BhiB + off);
                LDSM4(bl, BloB + off);
#pragma unroll
                for (int i = 0; i < 4; i++) {
                    MMA16816(d[i][2*jp],   ah[i], bh);
                    MMA16816(d[i][2*jp],   al[i], bh);
                    MMA16816(d[i][2*jp],   ah[i], bl);
                    MMA16816(d[i][2*jp+1], ah[i], bh + 2);
                    MMA16816(d[i][2*jp+1], al[i], bh + 2);
                    MMA16816(d[i][2*jp+1], ah[i], bl + 2);
                }
            }
        }
        __syncthreads();
    }

    const int trow = lane >> 2, tcol = (lane & 3) * 2;
#pragma unroll
    for (int i = 0; i < 4; i++)
#pragma unroll
        for (int j = 0; j < 8; j++) {
            float* p = C + (size_t)(m0 + wm + 16 * i + trow) * N
                         + (n0 + wn + 8 * j + tcol);
            p[0] = d[i][j][0]; p[1] = d[i][j][1];
            float* p2 = p + (size_t)8 * N;
            p2[0] = d[i][j][2]; p2[1] = d[i][j][3];
        }
}

// ============================================================================
// Fused RoPE + bf16 split for Q and K heads of packed qkv.
// ============================================================================
__global__ void rope_split_qk(const float* __restrict__ qkv,
                              const float* __restrict__ cosT,
                              const float* __restrict__ sinT,
                              __nv_bfloat16* __restrict__ qhi, __nv_bfloat16* __restrict__ qlo,
                              __nv_bfloat16* __restrict__ khi, __nv_bfloat16* __restrict__ klo)
{
    int idx = blockIdx.x * blockDim.x + threadIdx.x;
    if (idx >= SEQ * 20 * 64) return;
    int d  = idx & 63;
    int hh = (idx >> 6) % 20;
    int s  = idx / (20 * 64);
    const float* p = qkv + (size_t)s * QKVW + hh * HDIM;
    float x1 = p[d], x2 = p[d + 64];
    float c  = cosT[s * HDIM + d];
    float sn = sinT[s * HDIM + d];
    float y1 = fmaf(x1, c, -x2 * sn);
    float y2 = fmaf(x2, c,  x1 * sn);
    __nv_bfloat16 h1 = __float2bfloat16(y1), h2 = __float2bfloat16(y2);
    __nv_bfloat16 l1 = __float2bfloat16(y1 - __bfloat162float(h1));
    __nv_bfloat16 l2 = __float2bfloat16(y2 - __bfloat162float(h2));
    if (hh < NH) {
        size_t o = (size_t)s * QW + hh * HDIM;
        qhi[o + d] = h1; qhi[o + d + 64] = h2;
        qlo[o + d] = l1; qlo[o + d + 64] = l2;
    } else {
        size_t o = (size_t)s * KWW + (hh - NH) * HDIM;
        khi[o + d] = h1; khi[o + d + 64] = h2;
        klo[o + d] = l1; klo[o + d + 64] = l2;
    }
}

__global__ void split_v(const float* __restrict__ qkv,
                        __nv_bfloat16* __restrict__ vhi,
                        __nv_bfloat16* __restrict__ vlo)
{
    int idx = blockIdx.x * blockDim.x + threadIdx.x;
    if (idx >= SEQ * KWW) return;
    int c = idx & (KWW - 1);
    int s = idx >> 9;
    float x = qkv[(size_t)s * QKVW + QW + KWW + c];
    __nv_bfloat16 h = __float2bfloat16(x);
    vhi[(size_t)s * KWW + c] = h;
    vlo[(size_t)s * KWW + c] = __float2bfloat16(x - __bfloat162float(h));
}

// ============================================================================
// Tensor-core causal flash attention (bf16 3-term, fp32 softmax).
// CTA = 128 q-rows x 1 head, 8 warps x 16 rows, KV tiles 64 rows double-
// buffered. Q fragments cached in registers across all KV tiles.
// ============================================================================
#define BQ      128
#define BKV     64
#define FL_STR  136
#define FL_QT   (BQ * FL_STR * 2)
#define FL_KT   (BKV * FL_STR * 2)
#define FL_STG  (4 * FL_KT)
#define FLASH_SMEM (2 * FL_QT + 2 * FL_STG)

__global__ __launch_bounds__(256, 1) void flash_mma(
    const __nv_bfloat16* __restrict__ Qhi, const __nv_bfloat16* __restrict__ Qlo,
    const __nv_bfloat16* __restrict__ Khi, const __nv_bfloat16* __restrict__ Klo,
    const __nv_bfloat16* __restrict__ Vhi, const __nv_bfloat16* __restrict__ Vlo,
    __nv_bfloat16* __restrict__ Ohi, __nv_bfloat16* __restrict__ Olo)
{
    extern __shared__ char smem[];
    const uint32_t sbm = smem_u32(smem);
    const uint32_t QHI = sbm, QLO = sbm + FL_QT;
    const uint32_t ST0 = sbm + 2 * FL_QT;

    const int qt  = (int)gridDim.x - 1 - (int)blockIdx.x;
    const int h   = blockIdx.y;
    const int kvh = h >> 2;
    const int tid = threadIdx.x, wid = tid >> 5, lane = tid & 31;
    const int qbase = qt * BQ;
    const int wm  = wid * 16;
    const int nkt = 2 * qt + 2;
    const float scale = 0.08838834764831845f;

    const int a_row = lane & 15;
    const int a_cb  = ((lane >> 4) & 1) << 3;
    const int b_row = (lane & 7) + (((lane >> 4) & 1) << 3);
    const int b_cb  = ((lane >> 3) & 1) << 3;
    const int v_row = (lane & 7) + (((lane >> 3) & 1) << 3);
    const int v_cb  = ((lane >> 4) & 1) << 3;
    const int r0    = lane >> 2;
    const int colq  = (lane & 3) * 2;

    // ---- Q tile -> smem (group 0) ----
    {
        const size_t qoff = (size_t)qbase * QW + h * HDIM;
#pragma unroll
        for (int it = 0; it < 8; it++) {
            int idx = tid + it * 256;
            int r = idx >> 4, c = idx & 15;
            uint32_t d = (uint32_t)(r * FL_STR + c * 8) * 2;
            cp16(QHI + d, Qhi + qoff + (size_t)r * QW + c * 8);
            cp16(QLO + d, Qlo + qoff + (size_t)r * QW + c * 8);
        }
        CP_COMMIT();
    }

#define FL_LOAD(s, kb) do {                                                   \
    uint32_t stb_ = ST0 + (uint32_t)(s) * FL_STG;                             \
    const size_t ko_ = (size_t)(kb) * KWW + kvh * HDIM;                       \
    _Pragma("unroll")                                                         \
    for (int it = 0; it < 4; it++) {                                          \
        int idx = tid + it * 256;                                             \
        int r = idx >> 4, c = idx & 15;                                       \
        uint32_t d_ = (uint32_t)(r * FL_STR + c * 8) * 2;                     \
        const size_t so_ = ko_ + (size_t)r * KWW + c * 8;                     \
        cp16(stb_ + 0 * FL_KT + d_, Khi + so_);                               \
        cp16(stb_ + 1 * FL_KT + d_, Klo + so_);                               \
        cp16(stb_ + 2 * FL_KT + d_, Vhi + so_);                               \
        cp16(stb_ + 3 * FL_KT + d_, Vlo + so_);                               \
    }                                                                         \
    CP_COMMIT();                                                              \
} while (0)

    FL_LOAD(0, 0);                 // group 1

    // ---- cache Q fragments in registers (loaded once) ----
    uint32_t qh[8][4], ql[8][4];
    CP_WAIT(1);                    // Q group done
    __syncthreads();
#pragma unroll
    for (int ks = 0; ks < 8; ks++) {
        uint32_t qoff = (uint32_t)((wm + a_row) * FL_STR + ks * 16 + a_cb) * 2;
        LDSM4(qh[ks], QHI + qoff);
        LDSM4(ql[ks], QLO + qoff);
    }

    float m0 = -1e30f, m1 = -1e30f, l0 = 0.f, l1 = 0.f;
    float o[16][4];
#pragma unroll
    for (int j = 0; j < 16; j++)
#pragma unroll
        for (int q = 0; q < 4; q++) o[j][q] = 0.f;

    for (int kt = 0; kt < nkt; kt++) {
        if (kt + 1 < nkt) { FL_LOAD((kt + 1) & 1, (kt + 1) * BKV); CP_WAIT(1); }
        else              { CP_WAIT(0); }
        __syncthreads();

        const uint32_t stb = ST0 + (uint32_t)(kt & 1) * FL_STG;
        const uint32_t KH = stb, KL = stb + FL_KT;
        const uint32_t VH = stb + 2 * FL_KT, VL = stb + 3 * FL_KT;

        // ---- S = Q K^T (3-term) ----
        float s[8][4];
#pragma unroll
        for (int j = 0; j < 8; j++)
#pragma unroll
            for (int q = 0; q < 4; q++) s[j][q] = 0.f;

#pragma unroll
        for (int ks = 0; ks < 8; ks++) {
#pragma unroll
            for (int jp = 0; jp < 4; jp++) {
                uint32_t bh[4], bl[4];
                uint32_t koff = (uint32_t)((jp * 16 + b_row) * FL_STR + ks * 16 + b_cb) * 2;
                LDSM4(bh, KH + koff);
                LDSM4(bl, KL + koff);
                MMA16816(s[2*jp],   qh[ks], bh);
                MMA16816(s[2*jp],   ql[ks], bh);
                MMA16816(s[2*jp],   qh[ks], bl);
                MMA16816(s[2*jp+1], qh[ks], bh + 2);
                MMA16816(s[2*jp+1], ql[ks], bh + 2);
                MMA16816(s[2*jp+1], qh[ks], bl + 2);
            }
        }

        // ---- softmax ----
        const int kbase = kt * BKV;
        if (kbase + BKV - 1 > qbase + wm) {
            const int row0g = qbase + wm + r0, row1g = row0g + 8;
#pragma unroll
            for (int j = 0; j < 8; j++) {
                int c0 = kbase + j * 8 + colq, c1 = c0 + 1;
                s[j][0] = (c0 <= row0g) ? s[j][0] * scale : -1e30f;
                s[j][1] = (c1 <= row0g) ? s[j][1] * scale : -1e30f;
                s[j][2] = (c0 <= row1g) ? s[j][2] * scale : -1e30f;
                s[j][3] = (c1 <= row1g) ? s[j][3] * scale : -1e30f;
            }
        } else {
#pragma unroll
            for (int j = 0; j < 8; j++) {
                s[j][0] *= scale; s[j][1] *= scale;
                s[j][2] *= scale; s[j][3] *= scale;
            }
        }

        float rmax0 = -1e30f, rmax1 = -1e30f;
#pragma unroll
        for (int j = 0; j < 8; j++) {
            rmax0 = fmaxf(rmax0, fmaxf(s[j][0], s[j][1]));
            rmax1 = fmaxf(rmax1, fmaxf(s[j][2], s[j][3]));
        }
        rmax0 = fmaxf(rmax0, __shfl_xor_sync(0xffffffffu, rmax0, 1));
        rmax0 = fmaxf(rmax0, __shfl_xor_sync(0xffffffffu, rmax0, 2));
        rmax1 = fmaxf(rmax1, __shfl_xor_sync(0xffffffffu, rmax1, 1));
        rmax1 = fmaxf(rmax1, __shfl_xor_sync(0xffffffffu, rmax1, 2));

        float mn0 = fmaxf(m0, rmax0), mn1 = fmaxf(m1, rmax1);
        float al0 = __expf(m0 - mn0), al1 = __expf(m1 - mn1);
        m0 = mn0; m1 = mn1;

        float rs0 = 0.f, rs1 = 0.f;
#pragma unroll
        for (int j = 0; j < 8; j++) {
            s[j][0] = __expf(s[j][0] - mn0); rs0 += s[j][0];
            s[j][1] = __expf(s[j][1] - mn0); rs0 += s[j][1];
            s[j][2] = __expf(s[j][2] - mn1); rs1 += s[j][2];
            s[j][3] = __expf(s[j][3] - mn1); rs1 += s[j][3];
        }
        rs0 += __shfl_xor_sync(0xffffffffu, rs0, 1);
        rs0 += __shfl_xor_sync(0xffffffffu, rs0, 2);
        rs1 += __shfl_xor_sync(0xffffffffu, rs1, 1);
        rs1 += __shfl_xor_sync(0xffffffffu, rs1, 2);
        l0 = l0 * al0 + rs0;
        l1 = l1 * al1 + rs1;

#pragma unroll
        for (int j = 0; j < 16; j++) {
            o[j][0] *= al0; o[j][1] *= al0;
            o[j][2] *= al1; o[j][3] *= al1;
        }

        // ---- O += P V (P split in registers, 3-term) ----
#pragma unroll
        for (int t = 0; t < 4; t++) {
            uint32_t ph[4], pl[4];
            bsplit2(s[2*t][0],   s[2*t][1],   ph[0], pl[0]);
            bsplit2(s[2*t][2],   s[2*t][3],   ph[1], pl[1]);
            bsplit2(s[2*t+1][0], s[2*t+1][1], ph[2], pl[2]);
            bsplit2(s[2*t+1][2], s[2*t+1][3], ph[3], pl[3]);
#pragma unroll
            for (int jp = 0; jp < 8; jp++) {
                uint32_t vh[4], vl[4];
                uint32_t voff = (uint32_t)((t * 16 + v_row) * FL_STR
                                           + jp * 16 + v_cb) * 2;
                LDSM4T(vh, VH + voff);
                LDSM4T(vl, VL + voff);
                MMA16816(o[2*jp],   ph, vh);
                MMA16816(o[2*jp],   pl, vh);
                MMA16816(o[2*jp],   ph, vl);
                MMA16816(o[2*jp+1], ph, vh + 2);
                MMA16816(o[2*jp+1], pl, vh + 2);
                MMA16816(o[2*jp+1], ph, vl + 2);
            }
        }
        __syncthreads();
    }

    // ---- epilogue ----
    const float inv0 = 1.f / l0, inv1 = 1.f / l1;
    const int row0g = qbase + wm + r0;
    const size_t base0 = (size_t)row0g * QW + h * HDIM;
    const size_t base1 = base0 + (size_t)8 * QW;
#pragma unroll
    for (int j = 0; j < 16; j++) {
        int col = j * 8 + colq;
        uint32_t hp, lp;
        bsplit2(o[j][0] * inv0, o[j][1] * inv0, hp, lp);
        *(uint32_t*)(Ohi + base0 + col) = hp;
        *(uint32_t*)(Olo + base0 + col) = lp;
        bsplit2(o[j][2] * inv1, o[j][3] * inv1, hp, lp);
        *(uint32_t*)(Ohi + base1 + col) = hp;
        *(uint32_t*)(Olo + base1 + col) = lp;
    }
}

// ============================================================================
// Launch
// ============================================================================
extern "C" void kernel_launch(void* const* d_in, const int* in_sizes, int n_in,
                              void* d_out, int out_size)
{
    const float* hidden = (const float*)d_in[0];
    const float* cosT   = (const float*)d_in[1];
    const float* sinT   = (const float*)d_in[2];
    const float* wq     = (const float*)d_in[4];
    const float* wk     = (const float*)d_in[5];
    const float* wv     = (const float*)d_in[6];
    const float* wo     = (const float*)d_in[7];
    float* out = (float*)d_out;

    float* qkv;
    __nv_bfloat16 *h_hi, *h_lo, *w_hi, *w_lo, *wo_hi, *wo_lo;
    __nv_bfloat16 *q_hi, *q_lo, *k_hi, *k_lo, *v_hi, *v_lo, *a_hi, *a_lo;
    cudaGetSymbolAddress((void**)&qkv,   g_qkv);
    cudaGetSymbolAddress((void**)&h_hi,  g_h_hi);
    cudaGetSymbolAddress((void**)&h_lo,  g_h_lo);
    cudaGetSymbolAddress((void**)&w_hi,  g_w_hi);
    cudaGetSymbolAddress((void**)&w_lo,  g_w_lo);
    cudaGetSymbolAddress((void**)&wo_hi, g_wo_hi);
    cudaGetSymbolAddress((void**)&wo_lo, g_wo_lo);
    cudaGetSymbolAddress((void**)&q_hi,  g_q_hi);
    cudaGetSymbolAddress((void**)&q_lo,  g_q_lo);
    cudaGetSymbolAddress((void**)&k_hi,  g_k_hi);
    cudaGetSymbolAddress((void**)&k_lo,  g_k_lo);
    cudaGetSymbolAddress((void**)&v_hi,  g_v_hi);
    cudaGetSymbolAddress((void**)&v_lo,  g_v_lo);
    cudaGetSymbolAddress((void**)&a_hi,  g_a_hi);
    cudaGetSymbolAddress((void**)&a_lo,  g_a_lo);

    cudaFuncSetAttribute(gemm_bf16x3,
                         cudaFuncAttributeMaxDynamicSharedMemorySize, GEMM_SMEM);
    cudaFuncSetAttribute(flash_mma,
                         cudaFuncAttributeMaxDynamicSharedMemorySize, FLASH_SMEM);

#define SPLIT(src, dhi, dlo, n) \
    split_kernel<<<((n) / 4 + 255) / 256, 256>>>(src, dhi, dlo, n)

    SPLIT(hidden, h_hi, h_lo, SEQ * DM);
    SPLIT(wq, w_hi,                         w_lo,                         QW  * DM);
    SPLIT(wk, w_hi + (size_t)QW * DM,       w_lo + (size_t)QW * DM,       KWW * DM);
    SPLIT(wv, w_hi + (size_t)(QW+KWW) * DM, w_lo + (size_t)(QW+KWW) * DM, KWW * DM);
    SPLIT(wo, wo_hi, wo_lo, DM * QW);

    gemm_bf16x3<<<dim3(QKVW / 256, SEQ / 128), 256, GEMM_SMEM>>>(
        h_hi, h_lo, w_hi, w_lo, qkv, QKVW, DM);

    rope_split_qk<<<(SEQ * 20 * 64 + 255) / 256, 256>>>(
        qkv, cosT, sinT, q_hi, q_lo, k_hi, k_lo);
    split_v<<<(SEQ * KWW + 255) / 256, 256>>>(qkv, v_hi, v_lo);

    flash_mma<<<dim3(SEQ / BQ, NH), 256, FLASH_SMEM>>>(
        q_hi, q_lo, k_hi, k_lo, v_hi, v_lo, a_hi, a_lo);

    gemm_bf16x3<<<dim3(DM / 256, SEQ / 128), 256, GEMM_SMEM>>>(
        a_hi, a_lo, wo_hi, wo_lo, out, DM, DM);
}

// round 6
// speedup vs baseline: 4.5613x; 1.4082x over previous
#include <cuda_runtime.h>
#include <cuda_fp16.h>
#include <cstdint>
#include <math.h>

#define SEQ   4096
#define DM    2048
#define NH    16
#define NKV   4
#define HDIM  128
#define QW    (NH * HDIM)    /* 2048 */
#define KWW   (NKV * HDIM)   /* 512  */
#define QKVW  (QW + 2 * KWW) /* 3072 */

// ---------------- scratch (device globals; no allocations allowed) ----------
__device__ float g_qkv[SEQ * QKVW];          // fp32 packed [Q|K|V] from QKV GEMM
__device__ __half g_h_hi[SEQ * DM],  g_h_lo[SEQ * DM];
__device__ __half g_w_hi[QKVW * DM];         // weights: hi only (2-term scheme)
__device__ __half g_wo_hi[DM * QW];
__device__ __half g_q_hi[SEQ * QW],  g_q_lo[SEQ * QW];
__device__ __half g_k_hi[SEQ * KWW];
__device__ __half g_v_hi[SEQ * KWW];
__device__ __half g_a_hi[SEQ * QW],  g_a_lo[SEQ * QW];

// ---------------- helpers -----------------------------------------------------
__device__ __forceinline__ uint32_t smem_u32(const void* p) {
    uint32_t a;
    asm("{ .reg .u64 t; cvta.to.shared.u64 t, %1; cvt.u32.u64 %0, t; }"
        : "=r"(a) : "l"(p));
    return a;
}

__device__ __forceinline__ void cp16(uint32_t dst, const void* src) {
    asm volatile("cp.async.cg.shared.global [%0], [%1], 16;" :: "r"(dst), "l"(src));
}
#define CP_COMMIT() asm volatile("cp.async.commit_group;" ::: "memory")
#define CP_WAIT(n)  asm volatile("cp.async.wait_group %0;" :: "n"(n) : "memory")

#define LDSM4(r, addr)                                                        \
    asm volatile("ldmatrix.sync.aligned.m8n8.x4.shared.b16 {%0,%1,%2,%3}, [%4];" \
        : "=r"((r)[0]), "=r"((r)[1]), "=r"((r)[2]), "=r"((r)[3]) : "r"(addr))

#define LDSM4T(r, addr)                                                       \
    asm volatile("ldmatrix.sync.aligned.m8n8.x4.trans.shared.b16 {%0,%1,%2,%3}, [%4];" \
        : "=r"((r)[0]), "=r"((r)[1]), "=r"((r)[2]), "=r"((r)[3]) : "r"(addr))

#define MMA16816(d, a, b)                                                     \
    asm volatile("mma.sync.aligned.m16n8k16.row.col.f32.f16.f16.f32 "         \
        "{%0,%1,%2,%3}, {%4,%5,%6,%7}, {%8,%9}, {%0,%1,%2,%3};"               \
        : "+f"((d)[0]), "+f"((d)[1]), "+f"((d)[2]), "+f"((d)[3])              \
        : "r"((a)[0]), "r"((a)[1]), "r"((a)[2]), "r"((a)[3]),                 \
          "r"((b)[0]), "r"((b)[1]))

// split a pair of floats into fp16x2 hi and fp16x2 lo (residual)
__device__ __forceinline__ void hsplit2(float x, float y,
                                        uint32_t& hip, uint32_t& lop) {
    __half hx = __float2half_rn(x), hy = __float2half_rn(y);
    float rx = x - __half2float(hx), ry = y - __half2float(hy);
    __half2 hp = __halves2half2(hx, hy);
    __half2 lp = __floats2half2_rn(rx, ry);
    hip = *reinterpret_cast<uint32_t*>(&hp);
    lop = *reinterpret_cast<uint32_t*>(&lp);
}

// ============================================================================
// fp32 -> fp16 hi + fp16 lo (activations)
// ============================================================================
__global__ void split2_kernel(const float* __restrict__ x,
                              __half* __restrict__ hi,
                              __half* __restrict__ lo, int n)
{
    int i = (blockIdx.x * blockDim.x + threadIdx.x) * 4;
    if (i >= n) return;
    float4 v = *(const float4*)(x + i);
    uint32_t h0, l0, h1, l1;
    hsplit2(v.x, v.y, h0, l0);
    hsplit2(v.z, v.w, h1, l1);
    *(uint32_t*)(hi + i)     = h0; *(uint32_t*)(hi + i + 2) = h1;
    *(uint32_t*)(lo + i)     = l0; *(uint32_t*)(lo + i + 2) = l1;
}

// fp32 -> fp16 (weights, hi only)
__global__ void conv_kernel(const float* __restrict__ x,
                            __half* __restrict__ hi, int n)
{
    int i = (blockIdx.x * blockDim.x + threadIdx.x) * 4;
    if (i >= n) return;
    float4 v = *(const float4*)(x + i);
    __half2 a = __floats2half2_rn(v.x, v.y);
    __half2 b = __floats2half2_rn(v.z, v.w);
    *(uint32_t*)(hi + i)     = *reinterpret_cast<uint32_t*>(&a);
    *(uint32_t*)(hi + i + 2) = *reinterpret_cast<uint32_t*>(&b);
}

// ============================================================================
// mma.sync fp16 NT GEMM, 2-term split: C = Ahi Bhi^T + Alo Bhi^T.
// CTA tile 128(M)x256(N), BK=32, 8 warps 2Mx4N (64x64), 3-stage cp.async.
// ============================================================================
#define BK        32
#define LDS_PAD   40
#define A_TILE_B  (128 * LDS_PAD * 2)          /* 10240 */
#define B_TILE_B  (256 * LDS_PAD * 2)          /* 20480 */
#define STAGE_B   (2 * A_TILE_B + B_TILE_B)    /* 40960 */
#define NSTAGE    3
#define GEMM_SMEM (NSTAGE * STAGE_B)           /* 122880 */

__global__ __launch_bounds__(256, 1) void gemm_f16x2(
    const __half* __restrict__ Ahi, const __half* __restrict__ Alo,
    const __half* __restrict__ Bhi,
    float* __restrict__ C, int N, int K)
{
    extern __shared__ char smem[];
    const uint32_t sb = smem_u32(smem);
    const int tid  = threadIdx.x;
    const int wid  = tid >> 5, lane = tid & 31;
    const int m0   = blockIdx.y * 128, n0 = blockIdx.x * 256;
    const int wm   = (wid & 1) * 64;
    const int wn   = (wid >> 1) * 64;

    const __half* a_hi = Ahi + (size_t)m0 * K;
    const __half* a_lo = Alo + (size_t)m0 * K;
    const __half* b_hi = Bhi + (size_t)n0 * K;

    const int a_row_l = lane & 15;
    const int a_colb  = ((lane >> 4) & 1) << 3;
    const int b_row_l = (lane & 7) + (((lane >> 4) & 1) << 3);
    const int b_colb  = ((lane >> 3) & 1) << 3;

    float d[4][8][4];
#pragma unroll
    for (int i = 0; i < 4; i++)
#pragma unroll
        for (int j = 0; j < 8; j++)
#pragma unroll
            for (int q = 0; q < 4; q++) d[i][j][q] = 0.f;

    const int nk = K / BK;

#define LOAD_STAGE(s, k0) do {                                                \
    uint32_t stb = sb + (uint32_t)(s) * STAGE_B;                              \
    _Pragma("unroll")                                                         \
    for (int it = 0; it < 2; it++) {    /* A hi/lo: 128 rows x 4 chunks */    \
        int idx = tid + it * 256;                                             \
        int r = idx >> 2, c = idx & 3;                                        \
        uint32_t doff = (uint32_t)(r * LDS_PAD + c * 8) * 2;                  \
        size_t soff = (size_t)r * K + (k0) + c * 8;                           \
        cp16(stb + doff,            a_hi + soff);                             \
        cp16(stb + A_TILE_B + doff, a_lo + soff);                             \
    }                                                                         \
    _Pragma("unroll")                                                         \
    for (int it = 0; it < 4; it++) {    /* B hi: 256 rows x 4 chunks */       \
        int idx = tid + it * 256;                                             \
        int r = idx >> 2, c = idx & 3;                                        \
        uint32_t doff = (uint32_t)(r * LDS_PAD + c * 8) * 2;                  \
        size_t soff = (size_t)r * K + (k0) + c * 8;                           \
        cp16(stb + 2 * A_TILE_B + doff, b_hi + soff);                         \
    }                                                                         \
    CP_COMMIT();                                                              \
} while (0)

    LOAD_STAGE(0, 0);
    LOAD_STAGE(1, BK);

    for (int kt = 0; kt < nk; kt++) {
        if (kt + 2 < nk)      { LOAD_STAGE((kt + 2) % NSTAGE, (kt + 2) * BK); CP_WAIT(2); }
        else if (kt + 1 < nk) { CP_WAIT(1); }
        else                  { CP_WAIT(0); }
        __syncthreads();

        const uint32_t stb  = sb + (uint32_t)(kt % NSTAGE) * STAGE_B;
        const uint32_t AhiB = stb;
        const uint32_t AloB = stb + A_TILE_B;
        const uint32_t BhiB = stb + 2 * A_TILE_B;

#pragma unroll
        for (int ks = 0; ks < BK; ks += 16) {
            uint32_t ah[4][4], al[4][4];
#pragma unroll
            for (int i = 0; i < 4; i++) {
                uint32_t off = (uint32_t)((wm + 16 * i + a_row_l) * LDS_PAD
                                          + ks + a_colb) * 2;
                LDSM4(ah[i], AhiB + off);
                LDSM4(al[i], AloB + off);
            }
#pragma unroll
            for (int jp = 0; jp < 4; jp++) {
                uint32_t bh[4];
                uint32_t off = (uint32_t)((wn + 16 * jp + b_row_l) * LDS_PAD
                                          + ks + b_colb) * 2;
                LDSM4(bh, BhiB + off);
#pragma unroll
                for (int i = 0; i < 4; i++) {
                    MMA16816(d[i][2*jp],   ah[i], bh);
                    MMA16816(d[i][2*jp],   al[i], bh);
                    MMA16816(d[i][2*jp+1], ah[i], bh + 2);
                    MMA16816(d[i][2*jp+1], al[i], bh + 2);
                }
            }
        }
        __syncthreads();
    }

    const int trow = lane >> 2, tcol = (lane & 3) * 2;
#pragma unroll
    for (int i = 0; i < 4; i++)
#pragma unroll
        for (int j = 0; j < 8; j++) {
            float* p = C + (size_t)(m0 + wm + 16 * i + trow) * N
                         + (n0 + wn + 8 * j + tcol);
            p[0] = d[i][j][0]; p[1] = d[i][j][1];
            float* p2 = p + (size_t)8 * N;
            p2[0] = d[i][j][2]; p2[1] = d[i][j][3];
        }
}

// ============================================================================
// Fused RoPE + fp16 split for Q (hi+lo) and K (hi only) of packed qkv.
// ============================================================================
__global__ void rope_split_qk(const float* __restrict__ qkv,
                              const float* __restrict__ cosT,
                              const float* __restrict__ sinT,
                              __half* __restrict__ qhi, __half* __restrict__ qlo,
                              __half* __restrict__ khi)
{
    int idx = blockIdx.x * blockDim.x + threadIdx.x;
    if (idx >= SEQ * 20 * 64) return;
    int d  = idx & 63;
    int hh = (idx >> 6) % 20;
    int s  = idx / (20 * 64);
    const float* p = qkv + (size_t)s * QKVW + hh * HDIM;
    float x1 = p[d], x2 = p[d + 64];
    float c  = cosT[s * HDIM + d];
    float sn = sinT[s * HDIM + d];
    float y1 = fmaf(x1, c, -x2 * sn);
    float y2 = fmaf(x2, c,  x1 * sn);
    __half h1 = __float2half_rn(y1), h2 = __float2half_rn(y2);
    if (hh < NH) {
        size_t o = (size_t)s * QW + hh * HDIM;
        qhi[o + d] = h1; qhi[o + d + 64] = h2;
        qlo[o + d]      = __float2half_rn(y1 - __half2float(h1));
        qlo[o + d + 64] = __float2half_rn(y2 - __half2float(h2));
    } else {
        size_t o = (size_t)s * KWW + (hh - NH) * HDIM;
        khi[o + d] = h1; khi[o + d + 64] = h2;
    }
}

__global__ void split_v(const float* __restrict__ qkv,
                        __half* __restrict__ vhi)
{
    int idx = blockIdx.x * blockDim.x + threadIdx.x;
    if (idx >= SEQ * KWW) return;
    int c = idx & (KWW - 1);
    int s = idx >> 9;
    vhi[(size_t)s * KWW + c] =
        __float2half_rn(qkv[(size_t)s * QKVW + QW + KWW + c]);
}

// ============================================================================
// Tensor-core causal flash attention (fp16 2-term, fp32 softmax).
// CTA = 128 q-rows x 1 head, 8 warps x 16 rows. KV tiles 64 rows (K hi, V hi)
// double-buffered. Q hi/lo fragments cached in registers.
// ============================================================================
#define BQ      128
#define BKV     64
#define FL_STR  136
#define FL_QT   (BQ * FL_STR * 2)
#define FL_KT   (BKV * FL_STR * 2)
#define FL_STG  (2 * FL_KT)                   /* Khi + Vhi */
#define FLASH_SMEM (2 * FL_QT + 2 * FL_STG)

__global__ __launch_bounds__(256, 1) void flash_mma(
    const __half* __restrict__ Qhi, const __half* __restrict__ Qlo,
    const __half* __restrict__ Khi, const __half* __restrict__ Vhi,
    __half* __restrict__ Ohi, __half* __restrict__ Olo)
{
    extern __shared__ char smem[];
    const uint32_t sbm = smem_u32(smem);
    const uint32_t QHI = sbm, QLO = sbm + FL_QT;
    const uint32_t ST0 = sbm + 2 * FL_QT;

    const int qt  = (int)gridDim.x - 1 - (int)blockIdx.x;
    const int h   = blockIdx.y;
    const int kvh = h >> 2;
    const int tid = threadIdx.x, wid = tid >> 5, lane = tid & 31;
    const int qbase = qt * BQ;
    const int wm  = wid * 16;
    const int nkt = 2 * qt + 2;
    const float scale = 0.08838834764831845f;

    const int a_row = lane & 15;
    const int a_cb  = ((lane >> 4) & 1) << 3;
    const int b_row = (lane & 7) + (((lane >> 4) & 1) << 3);
    const int b_cb  = ((lane >> 3) & 1) << 3;
    const int v_row = (lane & 7) + (((lane >> 3) & 1) << 3);
    const int v_cb  = ((lane >> 4) & 1) << 3;
    const int r0    = lane >> 2;
    const int colq  = (lane & 3) * 2;

    // ---- Q tile -> smem (group 0) ----
    {
        const size_t qoff = (size_t)qbase * QW + h * HDIM;
#pragma unroll
        for (int it = 0; it < 8; it++) {
            int idx = tid + it * 256;
            int r = idx >> 4, c = idx & 15;
            uint32_t d = (uint32_t)(r * FL_STR + c * 8) * 2;
            cp16(QHI + d, Qhi + qoff + (size_t)r * QW + c * 8);
            cp16(QLO + d, Qlo + qoff + (size_t)r * QW + c * 8);
        }
        CP_COMMIT();
    }

#define FL_LOAD(s, kb) do {                                                   \
    uint32_t stb_ = ST0 + (uint32_t)(s) * FL_STG;                             \
    const size_t ko_ = (size_t)(kb) * KWW + kvh * HDIM;                       \
    _Pragma("unroll")                                                         \
    for (int it = 0; it < 4; it++) {                                          \
        int idx = tid + it * 256;                                             \
        int r = idx >> 4, c = idx & 15;                                       \
        uint32_t d_ = (uint32_t)(r * FL_STR + c * 8) * 2;                     \
        const size_t so_ = ko_ + (size_t)r * KWW + c * 8;                     \
        cp16(stb_ + 0 * FL_KT + d_, Khi + so_);                               \
        cp16(stb_ + 1 * FL_KT + d_, Vhi + so_);                               \
    }                                                                         \
    CP_COMMIT();                                                              \
} while (0)

    FL_LOAD(0, 0);

    // ---- cache Q fragments in registers ----
    uint32_t qh[8][4], ql[8][4];
    CP_WAIT(1);
    __syncthreads();
#pragma unroll
    for (int ks = 0; ks < 8; ks++) {
        uint32_t qoff = (uint32_t)((wm + a_row) * FL_STR + ks * 16 + a_cb) * 2;
        LDSM4(qh[ks], QHI + qoff);
        LDSM4(ql[ks], QLO + qoff);
    }

    float m0 = -1e30f, m1 = -1e30f, l0 = 0.f, l1 = 0.f;
    float o[16][4];
#pragma unroll
    for (int j = 0; j < 16; j++)
#pragma unroll
        for (int q = 0; q < 4; q++) o[j][q] = 0.f;

    for (int kt = 0; kt < nkt; kt++) {
        if (kt + 1 < nkt) { FL_LOAD((kt + 1) & 1, (kt + 1) * BKV); CP_WAIT(1); }
        else              { CP_WAIT(0); }
        __syncthreads();

        const uint32_t stb = ST0 + (uint32_t)(kt & 1) * FL_STG;
        const uint32_t KH = stb, VH = stb + FL_KT;

        // ---- S = Q K^T (2-term) ----
        float s[8][4];
#pragma unroll
        for (int j = 0; j < 8; j++)
#pragma unroll
            for (int q = 0; q < 4; q++) s[j][q] = 0.f;

#pragma unroll
        for (int ks = 0; ks < 8; ks++) {
#pragma unroll
            for (int jp = 0; jp < 4; jp++) {
                uint32_t bh[4];
                uint32_t koff = (uint32_t)((jp * 16 + b_row) * FL_STR + ks * 16 + b_cb) * 2;
                LDSM4(bh, KH + koff);
                MMA16816(s[2*jp],   qh[ks], bh);
                MMA16816(s[2*jp],   ql[ks], bh);
                MMA16816(s[2*jp+1], qh[ks], bh + 2);
                MMA16816(s[2*jp+1], ql[ks], bh + 2);
            }
        }

        // ---- softmax ----
        const int kbase = kt * BKV;
        if (kbase + BKV - 1 > qbase + wm) {
            const int row0g = qbase + wm + r0, row1g = row0g + 8;
#pragma unroll
            for (int j = 0; j < 8; j++) {
                int c0 = kbase + j * 8 + colq, c1 = c0 + 1;
                s[j][0] = (c0 <= row0g) ? s[j][0] * scale : -1e30f;
                s[j][1] = (c1 <= row0g) ? s[j][1] * scale : -1e30f;
                s[j][2] = (c0 <= row1g) ? s[j][2] * scale : -1e30f;
                s[j][3] = (c1 <= row1g) ? s[j][3] * scale : -1e30f;
            }
        } else {
#pragma unroll
            for (int j = 0; j < 8; j++) {
                s[j][0] *= scale; s[j][1] *= scale;
                s[j][2] *= scale; s[j][3] *= scale;
            }
        }

        float rmax0 = -1e30f, rmax1 = -1e30f;
#pragma unroll
        for (int j = 0; j < 8; j++) {
            rmax0 = fmaxf(rmax0, fmaxf(s[j][0], s[j][1]));
            rmax1 = fmaxf(rmax1, fmaxf(s[j][2], s[j][3]));
        }
        rmax0 = fmaxf(rmax0, __shfl_xor_sync(0xffffffffu, rmax0, 1));
        rmax0 = fmaxf(rmax0, __shfl_xor_sync(0xffffffffu, rmax0, 2));
        rmax1 = fmaxf(rmax1, __shfl_xor_sync(0xffffffffu, rmax1, 1));
        rmax1 = fmaxf(rmax1, __shfl_xor_sync(0xffffffffu, rmax1, 2));

        float mn0 = fmaxf(m0, rmax0), mn1 = fmaxf(m1, rmax1);
        float al0 = __expf(m0 - mn0), al1 = __expf(m1 - mn1);
        m0 = mn0; m1 = mn1;

        float rs0 = 0.f, rs1 = 0.f;
#pragma unroll
        for (int j = 0; j < 8; j++) {
            s[j][0] = __expf(s[j][0] - mn0); rs0 += s[j][0];
            s[j][1] = __expf(s[j][1] - mn0); rs0 += s[j][1];
            s[j][2] = __expf(s[j][2] - mn1); rs1 += s[j][2];
            s[j][3] = __expf(s[j][3] - mn1); rs1 += s[j][3];
        }
        rs0 += __shfl_xor_sync(0xffffffffu, rs0, 1);
        rs0 += __shfl_xor_sync(0xffffffffu, rs0, 2);
        rs1 += __shfl_xor_sync(0xffffffffu, rs1, 1);
        rs1 += __shfl_xor_sync(0xffffffffu, rs1, 2);
        l0 = l0 * al0 + rs0;
        l1 = l1 * al1 + rs1;

#pragma unroll
        for (int j = 0; j < 16; j++) {
            o[j][0] *= al0; o[j][1] *= al0;
            o[j][2] *= al1; o[j][3] *= al1;
        }

        // ---- O += P V (P hi/lo in registers, V hi; 2-term) ----
#pragma unroll
        for (int t = 0; t < 4; t++) {
            uint32_t ph[4], pl[4];
            hsplit2(s[2*t][0],   s[2*t][1],   ph[0], pl[0]);
            hsplit2(s[2*t][2],   s[2*t][3],   ph[1], pl[1]);
            hsplit2(s[2*t+1][0], s[2*t+1][1], ph[2], pl[2]);
            hsplit2(s[2*t+1][2], s[2*t+1][3], ph[3], pl[3]);
#pragma unroll
            for (int jp = 0; jp < 8; jp++) {
                uint32_t vh[4];
                uint32_t voff = (uint32_t)((t * 16 + v_row) * FL_STR
                                           + jp * 16 + v_cb) * 2;
                LDSM4T(vh, VH + voff);
                MMA16816(o[2*jp],   ph, vh);
                MMA16816(o[2*jp],   pl, vh);
                MMA16816(o[2*jp+1], ph, vh + 2);
                MMA16816(o[2*jp+1], pl, vh + 2);
            }
        }
        __syncthreads();
    }

    // ---- epilogue: normalize, fp16-split, store ----
    const float inv0 = 1.f / l0, inv1 = 1.f / l1;
    const int row0g = qbase + wm + r0;
    const size_t base0 = (size_t)row0g * QW + h * HDIM;
    const size_t base1 = base0 + (size_t)8 * QW;
#pragma unroll
    for (int j = 0; j < 16; j++) {
        int col = j * 8 + colq;
        uint32_t hp, lp;
        hsplit2(o[j][0] * inv0, o[j][1] * inv0, hp, lp);
        *(uint32_t*)(Ohi + base0 + col) = hp;
        *(uint32_t*)(Olo + base0 + col) = lp;
        hsplit2(o[j][2] * inv1, o[j][3] * inv1, hp, lp);
        *(uint32_t*)(Ohi + base1 + col) = hp;
        *(uint32_t*)(Olo + base1 + col) = lp;
    }
}

// ============================================================================
// Launch
// ============================================================================
extern "C" void kernel_launch(void* const* d_in, const int* in_sizes, int n_in,
                              void* d_out, int out_size)
{
    const float* hidden = (const float*)d_in[0];
    const float* cosT   = (const float*)d_in[1];
    const float* sinT   = (const float*)d_in[2];
    const float* wq     = (const float*)d_in[4];
    const float* wk     = (const float*)d_in[5];
    const float* wv     = (const float*)d_in[6];
    const float* wo     = (const float*)d_in[7];
    float* out = (float*)d_out;

    float* qkv;
    __half *h_hi, *h_lo, *w_hi, *wo_hi;
    __half *q_hi, *q_lo, *k_hi, *v_hi, *a_hi, *a_lo;
    cudaGetSymbolAddress((void**)&qkv,   g_qkv);
    cudaGetSymbolAddress((void**)&h_hi,  g_h_hi);
    cudaGetSymbolAddress((void**)&h_lo,  g_h_lo);
    cudaGetSymbolAddress((void**)&w_hi,  g_w_hi);
    cudaGetSymbolAddress((void**)&wo_hi, g_wo_hi);
    cudaGetSymbolAddress((void**)&q_hi,  g_q_hi);
    cudaGetSymbolAddress((void**)&q_lo,  g_q_lo);
    cudaGetSymbolAddress((void**)&k_hi,  g_k_hi);
    cudaGetSymbolAddress((void**)&v_hi,  g_v_hi);
    cudaGetSymbolAddress((void**)&a_hi,  g_a_hi);
    cudaGetSymbolAddress((void**)&a_lo,  g_a_lo);

    cudaFuncSetAttribute(gemm_f16x2,
                         cudaFuncAttributeMaxDynamicSharedMemorySize, GEMM_SMEM);
    cudaFuncSetAttribute(flash_mma,
                         cudaFuncAttributeMaxDynamicSharedMemorySize, FLASH_SMEM);

    split2_kernel<<<(SEQ * DM / 4 + 255) / 256, 256>>>(hidden, h_hi, h_lo, SEQ * DM);
    conv_kernel<<<(QW  * DM / 4 + 255) / 256, 256>>>(wq, w_hi, QW * DM);
    conv_kernel<<<(KWW * DM / 4 + 255) / 256, 256>>>(wk, w_hi + (size_t)QW * DM, KWW * DM);
    conv_kernel<<<(KWW * DM / 4 + 255) / 256, 256>>>(wv, w_hi + (size_t)(QW + KWW) * DM, KWW * DM);
    conv_kernel<<<(DM * QW / 4 + 255) / 256, 256>>>(wo, wo_hi, DM * QW);

    gemm_f16x2<<<dim3(QKVW / 256, SEQ / 128), 256, GEMM_SMEM>>>(
        h_hi, h_lo, w_hi, qkv, QKVW, DM);

    rope_split_qk<<<(SEQ * 20 * 64 + 255) / 256, 256>>>(
        qkv, cosT, sinT, q_hi, q_lo, k_hi);
    split_v<<<(SEQ * KWW + 255) / 256, 256>>>(qkv, v_hi);

    flash_mma<<<dim3(SEQ / BQ, NH), 256, FLASH_SMEM>>>(
        q_hi, q_lo, k_hi, v_hi, a_hi, a_lo);

    gemm_f16x2<<<dim3(DM / 256, SEQ / 128), 256, GEMM_SMEM>>>(
        a_hi, a_lo, wo_hi, out, DM, DM);
}

// round 7
// speedup vs baseline: 5.0340x; 1.1036x over previous
#include <cuda_runtime.h>
#include <cuda_fp16.h>
#include <cstdint>
#include <math.h>

#define SEQ   4096
#define DM    2048
#define NH    16
#define NKV   4
#define HDIM  128
#define QW    (NH * HDIM)    /* 2048 */
#define KWW   (NKV * HDIM)   /* 512  */
#define QKVW  (QW + 2 * KWW) /* 3072 */

// ---------------- scratch (device globals; no allocations allowed) ----------
__device__ float g_qkv[SEQ * QKVW];
__device__ __half g_h_hi[SEQ * DM],  g_h_lo[SEQ * DM];
__device__ __half g_w_hi[QKVW * DM];
__device__ __half g_wo_hi[DM * QW];
__device__ __half g_q_hi[SEQ * QW],  g_q_lo[SEQ * QW];
__device__ __half g_k_hi[SEQ * KWW];
__device__ __half g_v_hi[SEQ * KWW];
__device__ __half g_a_hi[SEQ * QW],  g_a_lo[SEQ * QW];

// ---------------- helpers -----------------------------------------------------
__device__ __forceinline__ uint32_t smem_u32(const void* p) {
    uint32_t a;
    asm("{ .reg .u64 t; cvta.to.shared.u64 t, %1; cvt.u32.u64 %0, t; }"
        : "=r"(a) : "l"(p));
    return a;
}

__device__ __forceinline__ void cp16(uint32_t dst, const void* src) {
    asm volatile("cp.async.cg.shared.global [%0], [%1], 16;" :: "r"(dst), "l"(src));
}
#define CP_COMMIT() asm volatile("cp.async.commit_group;" ::: "memory")
#define CP_WAIT(n)  asm volatile("cp.async.wait_group %0;" :: "n"(n) : "memory")

#define LDSM4(r, addr)                                                        \
    asm volatile("ldmatrix.sync.aligned.m8n8.x4.shared.b16 {%0,%1,%2,%3}, [%4];" \
        : "=r"((r)[0]), "=r"((r)[1]), "=r"((r)[2]), "=r"((r)[3]) : "r"(addr))

#define LDSM4T(r, addr)                                                       \
    asm volatile("ldmatrix.sync.aligned.m8n8.x4.trans.shared.b16 {%0,%1,%2,%3}, [%4];" \
        : "=r"((r)[0]), "=r"((r)[1]), "=r"((r)[2]), "=r"((r)[3]) : "r"(addr))

#define MMA16816(d, a, b)                                                     \
    asm volatile("mma.sync.aligned.m16n8k16.row.col.f32.f16.f16.f32 "         \
        "{%0,%1,%2,%3}, {%4,%5,%6,%7}, {%8,%9}, {%0,%1,%2,%3};"               \
        : "+f"((d)[0]), "+f"((d)[1]), "+f"((d)[2]), "+f"((d)[3])              \
        : "r"((a)[0]), "r"((a)[1]), "r"((a)[2]), "r"((a)[3]),                 \
          "r"((b)[0]), "r"((b)[1]))

__device__ __forceinline__ void hsplit2(float x, float y,
                                        uint32_t& hip, uint32_t& lop) {
    __half hx = __float2half_rn(x), hy = __float2half_rn(y);
    float rx = x - __half2float(hx), ry = y - __half2float(hy);
    __half2 hp = __halves2half2(hx, hy);
    __half2 lp = __floats2half2_rn(rx, ry);
    hip = *reinterpret_cast<uint32_t*>(&hp);
    lop = *reinterpret_cast<uint32_t*>(&lp);
}

__device__ __forceinline__ uint32_t hpack2(float x, float y) {
    __half2 hp = __floats2half2_rn(x, y);
    return *reinterpret_cast<uint32_t*>(&hp);
}

// ============================================================================
// fp32 -> fp16 hi + fp16 lo (activations)
// ============================================================================
__global__ void split2_kernel(const float* __restrict__ x,
                              __half* __restrict__ hi,
                              __half* __restrict__ lo, int n)
{
    int i = (blockIdx.x * blockDim.x + threadIdx.x) * 4;
    if (i >= n) return;
    float4 v = *(const float4*)(x + i);
    uint32_t h0, l0, h1, l1;
    hsplit2(v.x, v.y, h0, l0);
    hsplit2(v.z, v.w, h1, l1);
    *(uint32_t*)(hi + i)     = h0; *(uint32_t*)(hi + i + 2) = h1;
    *(uint32_t*)(lo + i)     = l0; *(uint32_t*)(lo + i + 2) = l1;
}

// ============================================================================
// fused weight conversion: wq|wk|wv -> g_w_hi, wo -> g_wo_hi (single launch)
// ============================================================================
#define N_WQ  (QW  * DM)
#define N_WK  (KWW * DM)
#define N_WV  (KWW * DM)
#define N_WO  (DM  * QW)
#define N_WTOT (N_WQ + N_WK + N_WV + N_WO)

__global__ void conv_w_fused(const float* __restrict__ wq,
                             const float* __restrict__ wk,
                             const float* __restrict__ wv,
                             const float* __restrict__ wo,
                             __half* __restrict__ w_hi,
                             __half* __restrict__ wo_hi)
{
    int i = (blockIdx.x * blockDim.x + threadIdx.x) * 4;
    if (i >= N_WTOT) return;
    const float* src; __half* dst; int off;
    if (i < N_WQ)                   { src = wq; dst = w_hi;                    off = i; }
    else if (i < N_WQ + N_WK)       { src = wk; dst = w_hi + N_WQ;             off = i - N_WQ; }
    else if (i < N_WQ + N_WK + N_WV){ src = wv; dst = w_hi + N_WQ + N_WK;      off = i - N_WQ - N_WK; }
    else                            { src = wo; dst = wo_hi;                   off = i - N_WQ - N_WK - N_WV; }
    float4 v = *(const float4*)(src + off);
    *(uint32_t*)(dst + off)     = hpack2(v.x, v.y);
    *(uint32_t*)(dst + off + 2) = hpack2(v.z, v.w);
}

// ============================================================================
// mma.sync fp16 NT GEMM, 2-term split: C = Ahi Bhi^T + Alo Bhi^T.
// CTA 128x256, BK=32, 8 warps 2Mx4N (64x64), 4-stage cp.async pipeline.
// ============================================================================
#define BK        32
#define LDS_PAD   40
#define A_TILE_B  (128 * LDS_PAD * 2)
#define B_TILE_B  (256 * LDS_PAD * 2)
#define STAGE_B   (2 * A_TILE_B + B_TILE_B)    /* 40960 */
#define NSTAGE    4
#define GEMM_SMEM (NSTAGE * STAGE_B)           /* 163840 */

__global__ __launch_bounds__(256, 1) void gemm_f16x2(
    const __half* __restrict__ Ahi, const __half* __restrict__ Alo,
    const __half* __restrict__ Bhi,
    float* __restrict__ C, int N, int K)
{
    extern __shared__ char smem[];
    const uint32_t sb = smem_u32(smem);
    const int tid  = threadIdx.x;
    const int wid  = tid >> 5, lane = tid & 31;
    const int m0   = blockIdx.y * 128, n0 = blockIdx.x * 256;
    const int wm   = (wid & 1) * 64;
    const int wn   = (wid >> 1) * 64;

    const __half* a_hi = Ahi + (size_t)m0 * K;
    const __half* a_lo = Alo + (size_t)m0 * K;
    const __half* b_hi = Bhi + (size_t)n0 * K;

    const int a_row_l = lane & 15;
    const int a_colb  = ((lane >> 4) & 1) << 3;
    const int b_row_l = (lane & 7) + (((lane >> 4) & 1) << 3);
    const int b_colb  = ((lane >> 3) & 1) << 3;

    float d[4][8][4];
#pragma unroll
    for (int i = 0; i < 4; i++)
#pragma unroll
        for (int j = 0; j < 8; j++)
#pragma unroll
            for (int q = 0; q < 4; q++) d[i][j][q] = 0.f;

    const int nk = K / BK;

#define LOAD_STAGE(s, k0) do {                                                \
    uint32_t stb = sb + (uint32_t)(s) * STAGE_B;                              \
    _Pragma("unroll")                                                         \
    for (int it = 0; it < 2; it++) {                                          \
        int idx = tid + it * 256;                                             \
        int r = idx >> 2, c = idx & 3;                                        \
        uint32_t doff = (uint32_t)(r * LDS_PAD + c * 8) * 2;                  \
        size_t soff = (size_t)r * K + (k0) + c * 8;                           \
        cp16(stb + doff,            a_hi + soff);                             \
        cp16(stb + A_TILE_B + doff, a_lo + soff);                             \
    }                                                                         \
    _Pragma("unroll")                                                         \
    for (int it = 0; it < 4; it++) {                                          \
        int idx = tid + it * 256;                                             \
        int r = idx >> 2, c = idx & 3;                                        \
        uint32_t doff = (uint32_t)(r * LDS_PAD + c * 8) * 2;                  \
        size_t soff = (size_t)r * K + (k0) + c * 8;                           \
        cp16(stb + 2 * A_TILE_B + doff, b_hi + soff);                         \
    }                                                                         \
    CP_COMMIT();                                                              \
} while (0)

    LOAD_STAGE(0, 0);
    LOAD_STAGE(1, BK);
    LOAD_STAGE(2, 2 * BK);

    for (int kt = 0; kt < nk; kt++) {
        if (kt + 3 < nk)      { LOAD_STAGE((kt + 3) % NSTAGE, (kt + 3) * BK); CP_WAIT(3); }
        else if (kt + 2 < nk) { CP_WAIT(2); }
        else if (kt + 1 < nk) { CP_WAIT(1); }
        else                  { CP_WAIT(0); }
        __syncthreads();

        const uint32_t stb  = sb + (uint32_t)(kt % NSTAGE) * STAGE_B;
        const uint32_t AhiB = stb;
        const uint32_t AloB = stb + A_TILE_B;
        const uint32_t BhiB = stb + 2 * A_TILE_B;

#pragma unroll
        for (int ks = 0; ks < BK; ks += 16) {
            uint32_t ah[4][4], al[4][4];
#pragma unroll
            for (int i = 0; i < 4; i++) {
                uint32_t off = (uint32_t)((wm + 16 * i + a_row_l) * LDS_PAD
                                          + ks + a_colb) * 2;
                LDSM4(ah[i], AhiB + off);
                LDSM4(al[i], AloB + off);
            }
#pragma unroll
            for (int jp = 0; jp < 4; jp++) {
                uint32_t bh[4];
                uint32_t off = (uint32_t)((wn + 16 * jp + b_row_l) * LDS_PAD
                                          + ks + b_colb) * 2;
                LDSM4(bh, BhiB + off);
#pragma unroll
                for (int i = 0; i < 4; i++) {
                    MMA16816(d[i][2*jp],   ah[i], bh);
                    MMA16816(d[i][2*jp],   al[i], bh);
                    MMA16816(d[i][2*jp+1], ah[i], bh + 2);
                    MMA16816(d[i][2*jp+1], al[i], bh + 2);
                }
            }
        }
        __syncthreads();
    }

    const int trow = lane >> 2, tcol = (lane & 3) * 2;
#pragma unroll
    for (int i = 0; i < 4; i++)
#pragma unroll
        for (int j = 0; j < 8; j++) {
            float* p = C + (size_t)(m0 + wm + 16 * i + trow) * N
                         + (n0 + wn + 8 * j + tcol);
            p[0] = d[i][j][0]; p[1] = d[i][j][1];
            float* p2 = p + (size_t)8 * N;
            p2[0] = d[i][j][2]; p2[1] = d[i][j][3];
        }
}

// ============================================================================
// Fused RoPE + fp16 split for Q (hi+lo) and K (hi) of packed qkv.
// ============================================================================
__global__ void rope_split_qk(const float* __restrict__ qkv,
                              const float* __restrict__ cosT,
                              const float* __restrict__ sinT,
                              __half* __restrict__ qhi, __half* __restrict__ qlo,
                              __half* __restrict__ khi)
{
    int idx = blockIdx.x * blockDim.x + threadIdx.x;
    if (idx >= SEQ * 20 * 64) return;
    int d  = idx & 63;
    int hh = (idx >> 6) % 20;
    int s  = idx / (20 * 64);
    const float* p = qkv + (size_t)s * QKVW + hh * HDIM;
    float x1 = p[d], x2 = p[d + 64];
    float c  = cosT[s * HDIM + d];
    float sn = sinT[s * HDIM + d];
    float y1 = fmaf(x1, c, -x2 * sn);
    float y2 = fmaf(x2, c,  x1 * sn);
    __half h1 = __float2half_rn(y1), h2 = __float2half_rn(y2);
    if (hh < NH) {
        size_t o = (size_t)s * QW + hh * HDIM;
        qhi[o + d] = h1; qhi[o + d + 64] = h2;
        qlo[o + d]      = __float2half_rn(y1 - __half2float(h1));
        qlo[o + d + 64] = __float2half_rn(y2 - __half2float(h2));
    } else {
        size_t o = (size_t)s * KWW + (hh - NH) * HDIM;
        khi[o + d] = h1; khi[o + d + 64] = h2;
    }
}

__global__ void split_v(const float* __restrict__ qkv,
                        __half* __restrict__ vhi)
{
    int idx = blockIdx.x * blockDim.x + threadIdx.x;
    if (idx >= SEQ * KWW) return;
    int c = idx & (KWW - 1);
    int s = idx >> 9;
    vhi[(size_t)s * KWW + c] =
        __float2half_rn(qkv[(size_t)s * QKVW + QW + KWW + c]);
}

// ============================================================================
// Tensor-core causal flash attention.
// CTA = 128 q-rows x head, 8 warps x 16 rows. KV super-tiles of 128 rows
// (double-buffered cp.async), processed as two 64-col sub-tiles per stage.
// S = QK^T 2-term (Qhi,Qlo); P·V single-term P (error-budget validated).
// ============================================================================
#define BQ      128
#define BKVO    128                            /* outer KV tile */
#define FL_STR  136
#define FL_QT   (BQ * FL_STR * 2)              /* 34816 */
#define FL_KT   (BKVO * FL_STR * 2)            /* 34816 */
#define FL_STG  (2 * FL_KT)                    /* Khi + Vhi = 69632 */
#define FLASH_SMEM (2 * FL_QT + 2 * FL_STG)    /* 208896 */

__global__ __launch_bounds__(256, 1) void flash_mma(
    const __half* __restrict__ Qhi, const __half* __restrict__ Qlo,
    const __half* __restrict__ Khi, const __half* __restrict__ Vhi,
    __half* __restrict__ Ohi, __half* __restrict__ Olo)
{
    extern __shared__ char smem[];
    const uint32_t sbm = smem_u32(smem);
    const uint32_t QHI = sbm, QLO = sbm + FL_QT;
    const uint32_t ST0 = sbm + 2 * FL_QT;

    const int qt  = (int)gridDim.x - 1 - (int)blockIdx.x;
    const int h   = blockIdx.y;
    const int kvh = h >> 2;
    const int tid = threadIdx.x, wid = tid >> 5, lane = tid & 31;
    const int qbase = qt * BQ;
    const int wm  = wid * 16;
    const int nkt = qt + 1;                    /* 128-row KV tiles */
    const float scale = 0.08838834764831845f;

    const int a_row = lane & 15;
    const int a_cb  = ((lane >> 4) & 1) << 3;
    const int b_row = (lane & 7) + (((lane >> 4) & 1) << 3);
    const int b_cb  = ((lane >> 3) & 1) << 3;
    const int v_row = (lane & 7) + (((lane >> 3) & 1) << 3);
    const int v_cb  = ((lane >> 4) & 1) << 3;
    const int r0    = lane >> 2;
    const int colq  = (lane & 3) * 2;

    // ---- Q tile -> smem ----
    {
        const size_t qoff = (size_t)qbase * QW + h * HDIM;
#pragma unroll
        for (int it = 0; it < 8; it++) {
            int idx = tid + it * 256;
            int r = idx >> 4, c = idx & 15;
            uint32_t d = (uint32_t)(r * FL_STR + c * 8) * 2;
            cp16(QHI + d, Qhi + qoff + (size_t)r * QW + c * 8);
            cp16(QLO + d, Qlo + qoff + (size_t)r * QW + c * 8);
        }
        CP_COMMIT();
    }

#define FL_LOAD(s, kb) do {                                                   \
    uint32_t stb_ = ST0 + (uint32_t)(s) * FL_STG;                             \
    const size_t ko_ = (size_t)(kb) * KWW + kvh * HDIM;                       \
    _Pragma("unroll")                                                         \
    for (int it = 0; it < 8; it++) {                                          \
        int idx = tid + it * 256;                                             \
        int r = idx >> 4, c = idx & 15;                                       \
        uint32_t d_ = (uint32_t)(r * FL_STR + c * 8) * 2;                     \
        const size_t so_ = ko_ + (size_t)r * KWW + c * 8;                     \
        cp16(stb_ + 0 * FL_KT + d_, Khi + so_);                               \
        cp16(stb_ + 1 * FL_KT + d_, Vhi + so_);                               \
    }                                                                         \
    CP_COMMIT();                                                              \
} while (0)

    FL_LOAD(0, 0);

    // ---- cache Q fragments in registers ----
    uint32_t qh[8][4], ql[8][4];
    CP_WAIT(1);
    __syncthreads();
#pragma unroll
    for (int ks = 0; ks < 8; ks++) {
        uint32_t qoff = (uint32_t)((wm + a_row) * FL_STR + ks * 16 + a_cb) * 2;
        LDSM4(qh[ks], QHI + qoff);
        LDSM4(ql[ks], QLO + qoff);
    }

    float m0 = -1e30f, m1 = -1e30f, l0 = 0.f, l1 = 0.f;
    float o[16][4];
#pragma unroll
    for (int j = 0; j < 16; j++)
#pragma unroll
        for (int q = 0; q < 4; q++) o[j][q] = 0.f;

    for (int kt = 0; kt < nkt; kt++) {
        if (kt + 1 < nkt) { FL_LOAD((kt + 1) & 1, (kt + 1) * BKVO); CP_WAIT(1); }
        else              { CP_WAIT(0); }
        __syncthreads();

        const uint32_t stb = ST0 + (uint32_t)(kt & 1) * FL_STG;

#pragma unroll
        for (int sub = 0; sub < 2; sub++) {
            const uint32_t KH = stb + (uint32_t)(sub * 64 * FL_STR * 2);
            const uint32_t VH = stb + FL_KT + (uint32_t)(sub * 64 * FL_STR * 2);
            const int kbase = kt * BKVO + sub * 64;

            // ---- S = Q K^T (2-term) ----
            float s[8][4];
#pragma unroll
            for (int j = 0; j < 8; j++)
#pragma unroll
                for (int q = 0; q < 4; q++) s[j][q] = 0.f;

#pragma unroll
            for (int ks = 0; ks < 8; ks++) {
#pragma unroll
                for (int jp = 0; jp < 4; jp++) {
                    uint32_t bh[4];
                    uint32_t koff = (uint32_t)((jp * 16 + b_row) * FL_STR
                                               + ks * 16 + b_cb) * 2;
                    LDSM4(bh, KH + koff);
                    MMA16816(s[2*jp],   qh[ks], bh);
                    MMA16816(s[2*jp],   ql[ks], bh);
                    MMA16816(s[2*jp+1], qh[ks], bh + 2);
                    MMA16816(s[2*jp+1], ql[ks], bh + 2);
                }
            }

            // ---- softmax ----
            if (kbase + 63 > qbase + wm) {     // warp-uniform diagonal check
                const int row0g = qbase + wm + r0, row1g = row0g + 8;
#pragma unroll
                for (int j = 0; j < 8; j++) {
                    int c0 = kbase + j * 8 + colq, c1 = c0 + 1;
                    s[j][0] = (c0 <= row0g) ? s[j][0] * scale : -1e30f;
                    s[j][1] = (c1 <= row0g) ? s[j][1] * scale : -1e30f;
                    s[j][2] = (c0 <= row1g) ? s[j][2] * scale : -1e30f;
                    s[j][3] = (c1 <= row1g) ? s[j][3] * scale : -1e30f;
                }
            } else {
#pragma unroll
                for (int j = 0; j < 8; j++) {
                    s[j][0] *= scale; s[j][1] *= scale;
                    s[j][2] *= scale; s[j][3] *= scale;
                }
            }

            float rmax0 = -1e30f, rmax1 = -1e30f;
#pragma unroll
            for (int j = 0; j < 8; j++) {
                rmax0 = fmaxf(rmax0, fmaxf(s[j][0], s[j][1]));
                rmax1 = fmaxf(rmax1, fmaxf(s[j][2], s[j][3]));
            }
            rmax0 = fmaxf(rmax0, __shfl_xor_sync(0xffffffffu, rmax0, 1));
            rmax0 = fmaxf(rmax0, __shfl_xor_sync(0xffffffffu, rmax0, 2));
            rmax1 = fmaxf(rmax1, __shfl_xor_sync(0xffffffffu, rmax1, 1));
            rmax1 = fmaxf(rmax1, __shfl_xor_sync(0xffffffffu, rmax1, 2));

            float mn0 = fmaxf(m0, rmax0), mn1 = fmaxf(m1, rmax1);
            float al0 = __expf(m0 - mn0), al1 = __expf(m1 - mn1);
            m0 = mn0; m1 = mn1;

            float rs0 = 0.f, rs1 = 0.f;
#pragma unroll
            for (int j = 0; j < 8; j++) {
                s[j][0] = __expf(s[j][0] - mn0); rs0 += s[j][0];
                s[j][1] = __expf(s[j][1] - mn0); rs0 += s[j][1];
                s[j][2] = __expf(s[j][2] - mn1); rs1 += s[j][2];
                s[j][3] = __expf(s[j][3] - mn1); rs1 += s[j][3];
            }
            rs0 += __shfl_xor_sync(0xffffffffu, rs0, 1);
            rs0 += __shfl_xor_sync(0xffffffffu, rs0, 2);
            rs1 += __shfl_xor_sync(0xffffffffu, rs1, 1);
            rs1 += __shfl_xor_sync(0xffffffffu, rs1, 2);
            l0 = l0 * al0 + rs0;
            l1 = l1 * al1 + rs1;

#pragma unroll
            for (int j = 0; j < 16; j++) {
                o[j][0] *= al0; o[j][1] *= al0;
                o[j][2] *= al1; o[j][3] *= al1;
            }

            // ---- O += P V (single-term P) ----
#pragma unroll
            for (int t = 0; t < 4; t++) {
                uint32_t ph[4];
                ph[0] = hpack2(s[2*t][0],   s[2*t][1]);
                ph[1] = hpack2(s[2*t][2],   s[2*t][3]);
                ph[2] = hpack2(s[2*t+1][0], s[2*t+1][1]);
                ph[3] = hpack2(s[2*t+1][2], s[2*t+1][3]);
#pragma unroll
                for (int jp = 0; jp < 8; jp++) {
                    uint32_t vh[4];
                    uint32_t voff = (uint32_t)((t * 16 + v_row) * FL_STR
                                               + jp * 16 + v_cb) * 2;
                    LDSM4T(vh, VH + voff);
                    MMA16816(o[2*jp],   ph, vh);
                    MMA16816(o[2*jp+1], ph, vh + 2);
                }
            }
        }
        __syncthreads();
    }

    // ---- epilogue: normalize, fp16-split, store ----
    const float inv0 = 1.f / l0, inv1 = 1.f / l1;
    const int row0g = qbase + wm + r0;
    const size_t base0 = (size_t)row0g * QW + h * HDIM;
    const size_t base1 = base0 + (size_t)8 * QW;
#pragma unroll
    for (int j = 0; j < 16; j++) {
        int col = j * 8 + colq;
        uint32_t hp, lp;
        hsplit2(o[j][0] * inv0, o[j][1] * inv0, hp, lp);
        *(uint32_t*)(Ohi + base0 + col) = hp;
        *(uint32_t*)(Olo + base0 + col) = lp;
        hsplit2(o[j][2] * inv1, o[j][3] * inv1, hp, lp);
        *(uint32_t*)(Ohi + base1 + col) = hp;
        *(uint32_t*)(Olo + base1 + col) = lp;
    }
}

// ============================================================================
// Launch
// ============================================================================
extern "C" void kernel_launch(void* const* d_in, const int* in_sizes, int n_in,
                              void* d_out, int out_size)
{
    const float* hidden = (const float*)d_in[0];
    const float* cosT   = (const float*)d_in[1];
    const float* sinT   = (const float*)d_in[2];
    const float* wq     = (const float*)d_in[4];
    const float* wk     = (const float*)d_in[5];
    const float* wv     = (const float*)d_in[6];
    const float* wo     = (const float*)d_in[7];
    float* out = (float*)d_out;

    float* qkv;
    __half *h_hi, *h_lo, *w_hi, *wo_hi;
    __half *q_hi, *q_lo, *k_hi, *v_hi, *a_hi, *a_lo;
    cudaGetSymbolAddress((void**)&qkv,   g_qkv);
    cudaGetSymbolAddress((void**)&h_hi,  g_h_hi);
    cudaGetSymbolAddress((void**)&h_lo,  g_h_lo);
    cudaGetSymbolAddress((void**)&w_hi,  g_w_hi);
    cudaGetSymbolAddress((void**)&wo_hi, g_wo_hi);
    cudaGetSymbolAddress((void**)&q_hi,  g_q_hi);
    cudaGetSymbolAddress((void**)&q_lo,  g_q_lo);
    cudaGetSymbolAddress((void**)&k_hi,  g_k_hi);
    cudaGetSymbolAddress((void**)&v_hi,  g_v_hi);
    cudaGetSymbolAddress((void**)&a_hi,  g_a_hi);
    cudaGetSymbolAddress((void**)&a_lo,  g_a_lo);

    cudaFuncSetAttribute(gemm_f16x2,
                         cudaFuncAttributeMaxDynamicSharedMemorySize, GEMM_SMEM);
    cudaFuncSetAttribute(flash_mma,
                         cudaFuncAttributeMaxDynamicSharedMemorySize, FLASH_SMEM);

    split2_kernel<<<(SEQ * DM / 4 + 255) / 256, 256>>>(hidden, h_hi, h_lo, SEQ * DM);
    conv_w_fused<<<(N_WTOT / 4 + 255) / 256, 256>>>(wq, wk, wv, wo, w_hi, wo_hi);

    gemm_f16x2<<<dim3(QKVW / 256, SEQ / 128), 256, GEMM_SMEM>>>(
        h_hi, h_lo, w_hi, qkv, QKVW, DM);

    rope_split_qk<<<(SEQ * 20 * 64 + 255) / 256, 256>>>(
        qkv, cosT, sinT, q_hi, q_lo, k_hi);
    split_v<<<(SEQ * KWW + 255) / 256, 256>>>(qkv, v_hi);

    flash_mma<<<dim3(SEQ / BQ, NH), 256, FLASH_SMEM>>>(
        q_hi, q_lo, k_hi, v_hi, a_hi, a_lo);

    gemm_f16x2<<<dim3(DM / 256, SEQ / 128), 256, GEMM_SMEM>>>(
        a_hi, a_lo, wo_hi, out, DM, DM);
}

// round 8
// speedup vs baseline: 6.5006x; 1.2913x over previous
#include <cuda_runtime.h>
#include <cuda_fp16.h>
#include <cstdint>
#include <math.h>

#define SEQ   4096
#define DM    2048
#define NH    16
#define NKV   4
#define HDIM  128
#define QW    (NH * HDIM)    /* 2048 */
#define KWW   (NKV * HDIM)   /* 512  */
#define QKVW  (QW + 2 * KWW) /* 3072 */

// ---------------- scratch (device globals; no allocations allowed) ----------
__device__ float g_qkv[SEQ * QKVW];
__device__ __half g_h_hi[SEQ * DM];
__device__ __half g_w_hi[QKVW * DM];
__device__ __half g_wo_hi[DM * QW];
__device__ __half g_q_hi[SEQ * QW],  g_q_lo[SEQ * QW];
__device__ __half g_k_hi[SEQ * KWW];
__device__ __half g_v_hi[SEQ * KWW];
__device__ __half g_a_hi[SEQ * QW];

// ---------------- helpers -----------------------------------------------------
__device__ __forceinline__ uint32_t smem_u32(const void* p) {
    uint32_t a;
    asm("{ .reg .u64 t; cvta.to.shared.u64 t, %1; cvt.u32.u64 %0, t; }"
        : "=r"(a) : "l"(p));
    return a;
}

__device__ __forceinline__ void cp16(uint32_t dst, const void* src) {
    asm volatile("cp.async.cg.shared.global [%0], [%1], 16;" :: "r"(dst), "l"(src));
}
#define CP_COMMIT() asm volatile("cp.async.commit_group;" ::: "memory")
#define CP_WAIT(n)  asm volatile("cp.async.wait_group %0;" :: "n"(n) : "memory")

#define LDSM4(r, addr)                                                        \
    asm volatile("ldmatrix.sync.aligned.m8n8.x4.shared.b16 {%0,%1,%2,%3}, [%4];" \
        : "=r"((r)[0]), "=r"((r)[1]), "=r"((r)[2]), "=r"((r)[3]) : "r"(addr))

#define LDSM4T(r, addr)                                                       \
    asm volatile("ldmatrix.sync.aligned.m8n8.x4.trans.shared.b16 {%0,%1,%2,%3}, [%4];" \
        : "=r"((r)[0]), "=r"((r)[1]), "=r"((r)[2]), "=r"((r)[3]) : "r"(addr))

#define MMA16816(d, a, b)                                                     \
    asm volatile("mma.sync.aligned.m16n8k16.row.col.f32.f16.f16.f32 "         \
        "{%0,%1,%2,%3}, {%4,%5,%6,%7}, {%8,%9}, {%0,%1,%2,%3};"               \
        : "+f"((d)[0]), "+f"((d)[1]), "+f"((d)[2]), "+f"((d)[3])              \
        : "r"((a)[0]), "r"((a)[1]), "r"((a)[2]), "r"((a)[3]),                 \
          "r"((b)[0]), "r"((b)[1]))

__device__ __forceinline__ uint32_t hpack2(float x, float y) {
    __half2 hp = __floats2half2_rn(x, y);
    return *reinterpret_cast<uint32_t*>(&hp);
}

// ============================================================================
// fp32 -> fp16 (hidden)
// ============================================================================
__global__ void conv_h(const float* __restrict__ x, __half* __restrict__ hi, int n)
{
    int i = (blockIdx.x * blockDim.x + threadIdx.x) * 4;
    if (i >= n) return;
    float4 v = *(const float4*)(x + i);
    *(uint32_t*)(hi + i)     = hpack2(v.x, v.y);
    *(uint32_t*)(hi + i + 2) = hpack2(v.z, v.w);
}

// ============================================================================
// fused weight conversion: wq|wk|wv -> g_w_hi, wo -> g_wo_hi
// ============================================================================
#define N_WQ  (QW  * DM)
#define N_WK  (KWW * DM)
#define N_WV  (KWW * DM)
#define N_WO  (DM  * QW)
#define N_WTOT (N_WQ + N_WK + N_WV + N_WO)

__global__ void conv_w_fused(const float* __restrict__ wq,
                             const float* __restrict__ wk,
                             const float* __restrict__ wv,
                             const float* __restrict__ wo,
                             __half* __restrict__ w_hi,
                             __half* __restrict__ wo_hi)
{
    int i = (blockIdx.x * blockDim.x + threadIdx.x) * 4;
    if (i >= N_WTOT) return;
    const float* src; __half* dst; int off;
    if (i < N_WQ)                   { src = wq; dst = w_hi;               off = i; }
    else if (i < N_WQ + N_WK)       { src = wk; dst = w_hi + N_WQ;        off = i - N_WQ; }
    else if (i < N_WQ + N_WK + N_WV){ src = wv; dst = w_hi + N_WQ + N_WK; off = i - N_WQ - N_WK; }
    else                            { src = wo; dst = wo_hi;              off = i - N_WQ - N_WK - N_WV; }
    float4 v = *(const float4*)(src + off);
    *(uint32_t*)(dst + off)     = hpack2(v.x, v.y);
    *(uint32_t*)(dst + off + 2) = hpack2(v.z, v.w);
}

// ============================================================================
// Pure fp16 mma.sync NT GEMM: C = A B^T.
// CTA 128x256, BK=32, 8 warps 2Mx4N (64x64), 4-stage cp.async pipeline.
// ============================================================================
#define BK        32
#define LDS_PAD   40
#define A_TILE_B  (128 * LDS_PAD * 2)          /* 10240 */
#define B_TILE_B  (256 * LDS_PAD * 2)          /* 20480 */
#define STAGE_B   (A_TILE_B + B_TILE_B)        /* 30720 */
#define NSTAGE    4
#define GEMM_SMEM (NSTAGE * STAGE_B)           /* 122880 */

__global__ __launch_bounds__(256, 1) void gemm_f16(
    const __half* __restrict__ A, const __half* __restrict__ B,
    float* __restrict__ C, int N, int K)
{
    extern __shared__ char smem[];
    const uint32_t sb = smem_u32(smem);
    const int tid  = threadIdx.x;
    const int wid  = tid >> 5, lane = tid & 31;
    const int m0   = blockIdx.y * 128, n0 = blockIdx.x * 256;
    const int wm   = (wid & 1) * 64;
    const int wn   = (wid >> 1) * 64;

    const __half* a_p = A + (size_t)m0 * K;
    const __half* b_p = B + (size_t)n0 * K;

    const int a_row_l = lane & 15;
    const int a_colb  = ((lane >> 4) & 1) << 3;
    const int b_row_l = (lane & 7) + (((lane >> 4) & 1) << 3);
    const int b_colb  = ((lane >> 3) & 1) << 3;

    float d[4][8][4];
#pragma unroll
    for (int i = 0; i < 4; i++)
#pragma unroll
        for (int j = 0; j < 8; j++)
#pragma unroll
            for (int q = 0; q < 4; q++) d[i][j][q] = 0.f;

    const int nk = K / BK;

#define LOAD_STAGE(s, k0) do {                                                \
    uint32_t stb = sb + (uint32_t)(s) * STAGE_B;                              \
    _Pragma("unroll")                                                         \
    for (int it = 0; it < 2; it++) {                                          \
        int idx = tid + it * 256;                                             \
        int r = idx >> 2, c = idx & 3;                                        \
        cp16(stb + (uint32_t)(r * LDS_PAD + c * 8) * 2,                       \
             a_p + (size_t)r * K + (k0) + c * 8);                             \
    }                                                                         \
    _Pragma("unroll")                                                         \
    for (int it = 0; it < 4; it++) {                                          \
        int idx = tid + it * 256;                                             \
        int r = idx >> 2, c = idx & 3;                                        \
        cp16(stb + A_TILE_B + (uint32_t)(r * LDS_PAD + c * 8) * 2,            \
             b_p + (size_t)r * K + (k0) + c * 8);                             \
    }                                                                         \
    CP_COMMIT();                                                              \
} while (0)

    LOAD_STAGE(0, 0);
    LOAD_STAGE(1, BK);
    LOAD_STAGE(2, 2 * BK);

    for (int kt = 0; kt < nk; kt++) {
        if (kt + 3 < nk)      { LOAD_STAGE((kt + 3) % NSTAGE, (kt + 3) * BK); CP_WAIT(3); }
        else if (kt + 2 < nk) { CP_WAIT(2); }
        else if (kt + 1 < nk) { CP_WAIT(1); }
        else                  { CP_WAIT(0); }
        __syncthreads();

        const uint32_t stb = sb + (uint32_t)(kt % NSTAGE) * STAGE_B;
        const uint32_t AB  = stb;
        const uint32_t BB  = stb + A_TILE_B;

#pragma unroll
        for (int ks = 0; ks < BK; ks += 16) {
            uint32_t ah[4][4];
#pragma unroll
            for (int i = 0; i < 4; i++) {
                uint32_t off = (uint32_t)((wm + 16 * i + a_row_l) * LDS_PAD
                                          + ks + a_colb) * 2;
                LDSM4(ah[i], AB + off);
            }
#pragma unroll
            for (int jp = 0; jp < 4; jp++) {
                uint32_t bh[4];
                uint32_t off = (uint32_t)((wn + 16 * jp + b_row_l) * LDS_PAD
                                          + ks + b_colb) * 2;
                LDSM4(bh, BB + off);
#pragma unroll
                for (int i = 0; i < 4; i++) {
                    MMA16816(d[i][2*jp],   ah[i], bh);
                    MMA16816(d[i][2*jp+1], ah[i], bh + 2);
                }
            }
        }
        __syncthreads();
    }

    const int trow = lane >> 2, tcol = (lane & 3) * 2;
#pragma unroll
    for (int i = 0; i < 4; i++)
#pragma unroll
        for (int j = 0; j < 8; j++) {
            float* p = C + (size_t)(m0 + wm + 16 * i + trow) * N
                         + (n0 + wn + 8 * j + tcol);
            p[0] = d[i][j][0]; p[1] = d[i][j][1];
            float* p2 = p + (size_t)8 * N;
            p2[0] = d[i][j][2]; p2[1] = d[i][j][3];
        }
}

// ============================================================================
// Fused RoPE + fp16 split for Q (hi+lo) and K (hi) of packed qkv.
// ============================================================================
__global__ void rope_split_qk(const float* __restrict__ qkv,
                              const float* __restrict__ cosT,
                              const float* __restrict__ sinT,
                              __half* __restrict__ qhi, __half* __restrict__ qlo,
                              __half* __restrict__ khi)
{
    int idx = blockIdx.x * blockDim.x + threadIdx.x;
    if (idx >= SEQ * 20 * 64) return;
    int d  = idx & 63;
    int hh = (idx >> 6) % 20;
    int s  = idx / (20 * 64);
    const float* p = qkv + (size_t)s * QKVW + hh * HDIM;
    float x1 = p[d], x2 = p[d + 64];
    float c  = cosT[s * HDIM + d];
    float sn = sinT[s * HDIM + d];
    float y1 = fmaf(x1, c, -x2 * sn);
    float y2 = fmaf(x2, c,  x1 * sn);
    __half h1 = __float2half_rn(y1), h2 = __float2half_rn(y2);
    if (hh < NH) {
        size_t o = (size_t)s * QW + hh * HDIM;
        qhi[o + d] = h1; qhi[o + d + 64] = h2;
        qlo[o + d]      = __float2half_rn(y1 - __half2float(h1));
        qlo[o + d + 64] = __float2half_rn(y2 - __half2float(h2));
    } else {
        size_t o = (size_t)s * KWW + (hh - NH) * HDIM;
        khi[o + d] = h1; khi[o + d + 64] = h2;
    }
}

__global__ void split_v(const float* __restrict__ qkv,
                        __half* __restrict__ vhi)
{
    int idx = blockIdx.x * blockDim.x + threadIdx.x;
    if (idx >= SEQ * KWW) return;
    int c = idx & (KWW - 1);
    int s = idx >> 9;
    vhi[(size_t)s * KWW + c] =
        __float2half_rn(qkv[(size_t)s * QKVW + QW + KWW + c]);
}

// ============================================================================
// Tensor-core causal flash attention.
// S = QK^T 2-term (Qhi,Qlo); P·V single-term. KV super-tiles 128 rows.
// Output: a_hi only (O-proj is pure fp16).
// ============================================================================
#define BQ      128
#define BKVO    128
#define FL_STR  136
#define FL_QT   (BQ * FL_STR * 2)
#define FL_KT   (BKVO * FL_STR * 2)
#define FL_STG  (2 * FL_KT)
#define FLASH_SMEM (2 * FL_QT + 2 * FL_STG)

__global__ __launch_bounds__(256, 1) void flash_mma(
    const __half* __restrict__ Qhi, const __half* __restrict__ Qlo,
    const __half* __restrict__ Khi, const __half* __restrict__ Vhi,
    __half* __restrict__ Ohi)
{
    extern __shared__ char smem[];
    const uint32_t sbm = smem_u32(smem);
    const uint32_t QHI = sbm, QLO = sbm + FL_QT;
    const uint32_t ST0 = sbm + 2 * FL_QT;

    const int qt  = (int)gridDim.x - 1 - (int)blockIdx.x;
    const int h   = blockIdx.y;
    const int kvh = h >> 2;
    const int tid = threadIdx.x, wid = tid >> 5, lane = tid & 31;
    const int qbase = qt * BQ;
    const int wm  = wid * 16;
    const int nkt = qt + 1;
    const float scale = 0.08838834764831845f;

    const int a_row = lane & 15;
    const int a_cb  = ((lane >> 4) & 1) << 3;
    const int b_row = (lane & 7) + (((lane >> 4) & 1) << 3);
    const int b_cb  = ((lane >> 3) & 1) << 3;
    const int v_row = (lane & 7) + (((lane >> 3) & 1) << 3);
    const int v_cb  = ((lane >> 4) & 1) << 3;
    const int r0    = lane >> 2;
    const int colq  = (lane & 3) * 2;

    {
        const size_t qoff = (size_t)qbase * QW + h * HDIM;
#pragma unroll
        for (int it = 0; it < 8; it++) {
            int idx = tid + it * 256;
            int r = idx >> 4, c = idx & 15;
            uint32_t d = (uint32_t)(r * FL_STR + c * 8) * 2;
            cp16(QHI + d, Qhi + qoff + (size_t)r * QW + c * 8);
            cp16(QLO + d, Qlo + qoff + (size_t)r * QW + c * 8);
        }
        CP_COMMIT();
    }

#define FL_LOAD(s, kb) do {                                                   \
    uint32_t stb_ = ST0 + (uint32_t)(s) * FL_STG;                             \
    const size_t ko_ = (size_t)(kb) * KWW + kvh * HDIM;                       \
    _Pragma("unroll")                                                         \
    for (int it = 0; it < 8; it++) {                                          \
        int idx = tid + it * 256;                                             \
        int r = idx >> 4, c = idx & 15;                                       \
        uint32_t d_ = (uint32_t)(r * FL_STR + c * 8) * 2;                     \
        const size_t so_ = ko_ + (size_t)r * KWW + c * 8;                     \
        cp16(stb_ + 0 * FL_KT + d_, Khi + so_);                               \
        cp16(stb_ + 1 * FL_KT + d_, Vhi + so_);                               \
    }                                                                         \
    CP_COMMIT();                                                              \
} while (0)

    FL_LOAD(0, 0);

    uint32_t qh[8][4], ql[8][4];
    CP_WAIT(1);
    __syncthreads();
#pragma unroll
    for (int ks = 0; ks < 8; ks++) {
        uint32_t qoff = (uint32_t)((wm + a_row) * FL_STR + ks * 16 + a_cb) * 2;
        LDSM4(qh[ks], QHI + qoff);
        LDSM4(ql[ks], QLO + qoff);
    }

    float m0 = -1e30f, m1 = -1e30f, l0 = 0.f, l1 = 0.f;
    float o[16][4];
#pragma unroll
    for (int j = 0; j < 16; j++)
#pragma unroll
        for (int q = 0; q < 4; q++) o[j][q] = 0.f;

    for (int kt = 0; kt < nkt; kt++) {
        if (kt + 1 < nkt) { FL_LOAD((kt + 1) & 1, (kt + 1) * BKVO); CP_WAIT(1); }
        else              { CP_WAIT(0); }
        __syncthreads();

        const uint32_t stb = ST0 + (uint32_t)(kt & 1) * FL_STG;

#pragma unroll
        for (int sub = 0; sub < 2; sub++) {
            const uint32_t KH = stb + (uint32_t)(sub * 64 * FL_STR * 2);
            const uint32_t VH = stb + FL_KT + (uint32_t)(sub * 64 * FL_STR * 2);
            const int kbase = kt * BKVO + sub * 64;

            float s[8][4];
#pragma unroll
            for (int j = 0; j < 8; j++)
#pragma unroll
                for (int q = 0; q < 4; q++) s[j][q] = 0.f;

#pragma unroll
            for (int ks = 0; ks < 8; ks++) {
#pragma unroll
                for (int jp = 0; jp < 4; jp++) {
                    uint32_t bh[4];
                    uint32_t koff = (uint32_t)((jp * 16 + b_row) * FL_STR
                                               + ks * 16 + b_cb) * 2;
                    LDSM4(bh, KH + koff);
                    MMA16816(s[2*jp],   qh[ks], bh);
                    MMA16816(s[2*jp],   ql[ks], bh);
                    MMA16816(s[2*jp+1], qh[ks], bh + 2);
                    MMA16816(s[2*jp+1], ql[ks], bh + 2);
                }
            }

            if (kbase + 63 > qbase + wm) {
                const int row0g = qbase + wm + r0, row1g = row0g + 8;
#pragma unroll
                for (int j = 0; j < 8; j++) {
                    int c0 = kbase + j * 8 + colq, c1 = c0 + 1;
                    s[j][0] = (c0 <= row0g) ? s[j][0] * scale : -1e30f;
                    s[j][1] = (c1 <= row0g) ? s[j][1] * scale : -1e30f;
                    s[j][2] = (c0 <= row1g) ? s[j][2] * scale : -1e30f;
                    s[j][3] = (c1 <= row1g) ? s[j][3] * scale : -1e30f;
                }
            } else {
#pragma unroll
                for (int j = 0; j < 8; j++) {
                    s[j][0] *= scale; s[j][1] *= scale;
                    s[j][2] *= scale; s[j][3] *= scale;
                }
            }

            float rmax0 = -1e30f, rmax1 = -1e30f;
#pragma unroll
            for (int j = 0; j < 8; j++) {
                rmax0 = fmaxf(rmax0, fmaxf(s[j][0], s[j][1]));
                rmax1 = fmaxf(rmax1, fmaxf(s[j][2], s[j][3]));
            }
            rmax0 = fmaxf(rmax0, __shfl_xor_sync(0xffffffffu, rmax0, 1));
            rmax0 = fmaxf(rmax0, __shfl_xor_sync(0xffffffffu, rmax0, 2));
            rmax1 = fmaxf(rmax1, __shfl_xor_sync(0xffffffffu, rmax1, 1));
            rmax1 = fmaxf(rmax1, __shfl_xor_sync(0xffffffffu, rmax1, 2));

            float mn0 = fmaxf(m0, rmax0), mn1 = fmaxf(m1, rmax1);
            float al0 = __expf(m0 - mn0), al1 = __expf(m1 - mn1);
            m0 = mn0; m1 = mn1;

            float rs0 = 0.f, rs1 = 0.f;
#pragma unroll
            for (int j = 0; j < 8; j++) {
                s[j][0] = __expf(s[j][0] - mn0); rs0 += s[j][0];
                s[j][1] = __expf(s[j][1] - mn0); rs0 += s[j][1];
                s[j][2] = __expf(s[j][2] - mn1); rs1 += s[j][2];
                s[j][3] = __expf(s[j][3] - mn1); rs1 += s[j][3];
            }
            rs0 += __shfl_xor_sync(0xffffffffu, rs0, 1);
            rs0 += __shfl_xor_sync(0xffffffffu, rs0, 2);
            rs1 += __shfl_xor_sync(0xffffffffu, rs1, 1);
            rs1 += __shfl_xor_sync(0xffffffffu, rs1, 2);
            l0 = l0 * al0 + rs0;
            l1 = l1 * al1 + rs1;

#pragma unroll
            for (int j = 0; j < 16; j++) {
                o[j][0] *= al0; o[j][1] *= al0;
                o[j][2] *= al1; o[j][3] *= al1;
            }

#pragma unroll
            for (int t = 0; t < 4; t++) {
                uint32_t ph[4];
                ph[0] = hpack2(s[2*t][0],   s[2*t][1]);
                ph[1] = hpack2(s[2*t][2],   s[2*t][3]);
                ph[2] = hpack2(s[2*t+1][0], s[2*t+1][1]);
                ph[3] = hpack2(s[2*t+1][2], s[2*t+1][3]);
#pragma unroll
                for (int jp = 0; jp < 8; jp++) {
                    uint32_t vh[4];
                    uint32_t voff = (uint32_t)((t * 16 + v_row) * FL_STR
                                               + jp * 16 + v_cb) * 2;
                    LDSM4T(vh, VH + voff);
                    MMA16816(o[2*jp],   ph, vh);
                    MMA16816(o[2*jp+1], ph, vh + 2);
                }
            }
        }
        __syncthreads();
    }

    const float inv0 = 1.f / l0, inv1 = 1.f / l1;
    const int row0g = qbase + wm + r0;
    const size_t base0 = (size_t)row0g * QW + h * HDIM;
    const size_t base1 = base0 + (size_t)8 * QW;
#pragma unroll
    for (int j = 0; j < 16; j++) {
        int col = j * 8 + colq;
        *(uint32_t*)(Ohi + base0 + col) = hpack2(o[j][0] * inv0, o[j][1] * inv0);
        *(uint32_t*)(Ohi + base1 + col) = hpack2(o[j][2] * inv1, o[j][3] * inv1);
    }
}

// ============================================================================
// Launch
// ============================================================================
extern "C" void kernel_launch(void* const* d_in, const int* in_sizes, int n_in,
                              void* d_out, int out_size)
{
    const float* hidden = (const float*)d_in[0];
    const float* cosT   = (const float*)d_in[1];
    const float* sinT   = (const float*)d_in[2];
    const float* wq     = (const float*)d_in[4];
    const float* wk     = (const float*)d_in[5];
    const float* wv     = (const float*)d_in[6];
    const float* wo     = (const float*)d_in[7];
    float* out = (float*)d_out;

    float* qkv;
    __half *h_hi, *w_hi, *wo_hi;
    __half *q_hi, *q_lo, *k_hi, *v_hi, *a_hi;
    cudaGetSymbolAddress((void**)&qkv,   g_qkv);
    cudaGetSymbolAddress((void**)&h_hi,  g_h_hi);
    cudaGetSymbolAddress((void**)&w_hi,  g_w_hi);
    cudaGetSymbolAddress((void**)&wo_hi, g_wo_hi);
    cudaGetSymbolAddress((void**)&q_hi,  g_q_hi);
    cudaGetSymbolAddress((void**)&q_lo,  g_q_lo);
    cudaGetSymbolAddress((void**)&k_hi,  g_k_hi);
    cudaGetSymbolAddress((void**)&v_hi,  g_v_hi);
    cudaGetSymbolAddress((void**)&a_hi,  g_a_hi);

    cudaFuncSetAttribute(gemm_f16,
                         cudaFuncAttributeMaxDynamicSharedMemorySize, GEMM_SMEM);
    cudaFuncSetAttribute(flash_mma,
                         cudaFuncAttributeMaxDynamicSharedMemorySize, FLASH_SMEM);

    conv_h<<<(SEQ * DM / 4 + 255) / 256, 256>>>(hidden, h_hi, SEQ * DM);
    conv_w_fused<<<(N_WTOT / 4 + 255) / 256, 256>>>(wq, wk, wv, wo, w_hi, wo_hi);

    gemm_f16<<<dim3(QKVW / 256, SEQ / 128), 256, GEMM_SMEM>>>(
        h_hi, w_hi, qkv, QKVW, DM);

    rope_split_qk<<<(SEQ * 20 * 64 + 255) / 256, 256>>>(
        qkv, cosT, sinT, q_hi, q_lo, k_hi);
    split_v<<<(SEQ * KWW + 255) / 256, 256>>>(qkv, v_hi);

    flash_mma<<<dim3(SEQ / BQ, NH), 256, FLASH_SMEM>>>(
        q_hi, q_lo, k_hi, v_hi, a_hi);

    gemm_f16<<<dim3(DM / 256, SEQ / 128), 256, GEMM_SMEM>>>(
        a_hi, wo_hi, out, DM, DM);
}

// round 9
// speedup vs baseline: 7.2324x; 1.1126x over previous
#include <cuda_runtime.h>
#include <cuda_fp16.h>
#include <cstdint>
#include <math.h>

#define SEQ   4096
#define DM    2048
#define NH    16
#define NKV   4
#define HDIM  128
#define QW    (NH * HDIM)    /* 2048 */
#define KWW   (NKV * HDIM)   /* 512  */
#define QKVW  (QW + 2 * KWW) /* 3072 */

// ---------------- scratch (device globals; no allocations allowed) ----------
__device__ float g_qkv[SEQ * QKVW];
__device__ __half g_h_hi[SEQ * DM];
__device__ __half g_w_hi[QKVW * DM];
__device__ __half g_wo_hi[DM * QW];
__device__ __half g_q_hi[SEQ * QW];
__device__ __half g_k_hi[SEQ * KWW];
__device__ __half g_v_hi[SEQ * KWW];
__device__ __half g_a_hi[SEQ * QW];

// ---------------- helpers -----------------------------------------------------
__device__ __forceinline__ uint32_t smem_u32(const void* p) {
    uint32_t a;
    asm("{ .reg .u64 t; cvta.to.shared.u64 t, %1; cvt.u32.u64 %0, t; }"
        : "=r"(a) : "l"(p));
    return a;
}

__device__ __forceinline__ void cp16(uint32_t dst, const void* src) {
    asm volatile("cp.async.cg.shared.global [%0], [%1], 16;" :: "r"(dst), "l"(src));
}
#define CP_COMMIT() asm volatile("cp.async.commit_group;" ::: "memory")
#define CP_WAIT(n)  asm volatile("cp.async.wait_group %0;" :: "n"(n) : "memory")

#define LDSM4(r, addr)                                                        \
    asm volatile("ldmatrix.sync.aligned.m8n8.x4.shared.b16 {%0,%1,%2,%3}, [%4];" \
        : "=r"((r)[0]), "=r"((r)[1]), "=r"((r)[2]), "=r"((r)[3]) : "r"(addr))

#define LDSM4T(r, addr)                                                       \
    asm volatile("ldmatrix.sync.aligned.m8n8.x4.trans.shared.b16 {%0,%1,%2,%3}, [%4];" \
        : "=r"((r)[0]), "=r"((r)[1]), "=r"((r)[2]), "=r"((r)[3]) : "r"(addr))

#define MMA16816(d, a, b)                                                     \
    asm volatile("mma.sync.aligned.m16n8k16.row.col.f32.f16.f16.f32 "         \
        "{%0,%1,%2,%3}, {%4,%5,%6,%7}, {%8,%9}, {%0,%1,%2,%3};"               \
        : "+f"((d)[0]), "+f"((d)[1]), "+f"((d)[2]), "+f"((d)[3])              \
        : "r"((a)[0]), "r"((a)[1]), "r"((a)[2]), "r"((a)[3]),                 \
          "r"((b)[0]), "r"((b)[1]))

__device__ __forceinline__ uint32_t hpack2(float x, float y) {
    __half2 hp = __floats2half2_rn(x, y);
    return *reinterpret_cast<uint32_t*>(&hp);
}

// ============================================================================
// fp32 -> fp16 (hidden)
// ============================================================================
__global__ void conv_h(const float* __restrict__ x, __half* __restrict__ hi, int n)
{
    int i = (blockIdx.x * blockDim.x + threadIdx.x) * 4;
    if (i >= n) return;
    float4 v = *(const float4*)(x + i);
    *(uint32_t*)(hi + i)     = hpack2(v.x, v.y);
    *(uint32_t*)(hi + i + 2) = hpack2(v.z, v.w);
}

// ============================================================================
// fused weight conversion: wq|wk|wv -> g_w_hi, wo -> g_wo_hi
// ============================================================================
#define N_WQ  (QW  * DM)
#define N_WK  (KWW * DM)
#define N_WV  (KWW * DM)
#define N_WO  (DM  * QW)
#define N_WTOT (N_WQ + N_WK + N_WV + N_WO)

__global__ void conv_w_fused(const float* __restrict__ wq,
                             const float* __restrict__ wk,
                             const float* __restrict__ wv,
                             const float* __restrict__ wo,
                             __half* __restrict__ w_hi,
                             __half* __restrict__ wo_hi)
{
    int i = (blockIdx.x * blockDim.x + threadIdx.x) * 4;
    if (i >= N_WTOT) return;
    const float* src; __half* dst; int off;
    if (i < N_WQ)                   { src = wq; dst = w_hi;               off = i; }
    else if (i < N_WQ + N_WK)       { src = wk; dst = w_hi + N_WQ;        off = i - N_WQ; }
    else if (i < N_WQ + N_WK + N_WV){ src = wv; dst = w_hi + N_WQ + N_WK; off = i - N_WQ - N_WK; }
    else                            { src = wo; dst = wo_hi;              off = i - N_WQ - N_WK - N_WV; }
    float4 v = *(const float4*)(src + off);
    *(uint32_t*)(dst + off)     = hpack2(v.x, v.y);
    *(uint32_t*)(dst + off + 2) = hpack2(v.z, v.w);
}

// ============================================================================
// Pure fp16 mma.sync NT GEMM: C = A B^T.
// CTA 128x256, BK=32, 8 warps 2Mx4N (64x64), 4-stage cp.async pipeline.
// ============================================================================
#define BK        32
#define LDS_PAD   40
#define A_TILE_B  (128 * LDS_PAD * 2)
#define B_TILE_B  (256 * LDS_PAD * 2)
#define STAGE_B   (A_TILE_B + B_TILE_B)
#define NSTAGE    4
#define GEMM_SMEM (NSTAGE * STAGE_B)

__global__ __launch_bounds__(256, 1) void gemm_f16(
    const __half* __restrict__ A, const __half* __restrict__ B,
    float* __restrict__ C, int N, int K)
{
    extern __shared__ char smem[];
    const uint32_t sb = smem_u32(smem);
    const int tid  = threadIdx.x;
    const int wid  = tid >> 5, lane = tid & 31;
    const int m0   = blockIdx.y * 128, n0 = blockIdx.x * 256;
    const int wm   = (wid & 1) * 64;
    const int wn   = (wid >> 1) * 64;

    const __half* a_p = A + (size_t)m0 * K;
    const __half* b_p = B + (size_t)n0 * K;

    const int a_row_l = lane & 15;
    const int a_colb  = ((lane >> 4) & 1) << 3;
    const int b_row_l = (lane & 7) + (((lane >> 4) & 1) << 3);
    const int b_colb  = ((lane >> 3) & 1) << 3;

    float d[4][8][4];
#pragma unroll
    for (int i = 0; i < 4; i++)
#pragma unroll
        for (int j = 0; j < 8; j++)
#pragma unroll
            for (int q = 0; q < 4; q++) d[i][j][q] = 0.f;

    const int nk = K / BK;

#define LOAD_STAGE(s, k0) do {                                                \
    uint32_t stb = sb + (uint32_t)(s) * STAGE_B;                              \
    _Pragma("unroll")                                                         \
    for (int it = 0; it < 2; it++) {                                          \
        int idx = tid + it * 256;                                             \
        int r = idx >> 2, c = idx & 3;                                        \
        cp16(stb + (uint32_t)(r * LDS_PAD + c * 8) * 2,                       \
             a_p + (size_t)r * K + (k0) + c * 8);                             \
    }                                                                         \
    _Pragma("unroll")                                                         \
    for (int it = 0; it < 4; it++) {                                          \
        int idx = tid + it * 256;                                             \
        int r = idx >> 2, c = idx & 3;                                        \
        cp16(stb + A_TILE_B + (uint32_t)(r * LDS_PAD + c * 8) * 2,            \
             b_p + (size_t)r * K + (k0) + c * 8);                             \
    }                                                                         \
    CP_COMMIT();                                                              \
} while (0)

    LOAD_STAGE(0, 0);
    LOAD_STAGE(1, BK);
    LOAD_STAGE(2, 2 * BK);

    for (int kt = 0; kt < nk; kt++) {
        if (kt + 3 < nk)      { LOAD_STAGE((kt + 3) % NSTAGE, (kt + 3) * BK); CP_WAIT(3); }
        else if (kt + 2 < nk) { CP_WAIT(2); }
        else if (kt + 1 < nk) { CP_WAIT(1); }
        else                  { CP_WAIT(0); }
        __syncthreads();

        const uint32_t stb = sb + (uint32_t)(kt % NSTAGE) * STAGE_B;
        const uint32_t AB  = stb;
        const uint32_t BB  = stb + A_TILE_B;

#pragma unroll
        for (int ks = 0; ks < BK; ks += 16) {
            uint32_t ah[4][4];
#pragma unroll
            for (int i = 0; i < 4; i++) {
                uint32_t off = (uint32_t)((wm + 16 * i + a_row_l) * LDS_PAD
                                          + ks + a_colb) * 2;
                LDSM4(ah[i], AB + off);
            }
#pragma unroll
            for (int jp = 0; jp < 4; jp++) {
                uint32_t bh[4];
                uint32_t off = (uint32_t)((wn + 16 * jp + b_row_l) * LDS_PAD
                                          + ks + b_colb) * 2;
                LDSM4(bh, BB + off);
#pragma unroll
                for (int i = 0; i < 4; i++) {
                    MMA16816(d[i][2*jp],   ah[i], bh);
                    MMA16816(d[i][2*jp+1], ah[i], bh + 2);
                }
            }
        }
        __syncthreads();
    }

    const int trow = lane >> 2, tcol = (lane & 3) * 2;
#pragma unroll
    for (int i = 0; i < 4; i++)
#pragma unroll
        for (int j = 0; j < 8; j++) {
            float* p = C + (size_t)(m0 + wm + 16 * i + trow) * N
                         + (n0 + wn + 8 * j + tcol);
            p[0] = d[i][j][0]; p[1] = d[i][j][1];
            float* p2 = p + (size_t)8 * N;
            p2[0] = d[i][j][2]; p2[1] = d[i][j][3];
        }
}

// ============================================================================
// Fused RoPE + fp16 convert for Q and K of packed qkv (hi only).
// ============================================================================
__global__ void rope_conv_qk(const float* __restrict__ qkv,
                             const float* __restrict__ cosT,
                             const float* __restrict__ sinT,
                             __half* __restrict__ qhi, __half* __restrict__ khi)
{
    int idx = blockIdx.x * blockDim.x + threadIdx.x;
    if (idx >= SEQ * 20 * 64) return;
    int d  = idx & 63;
    int hh = (idx >> 6) % 20;
    int s  = idx / (20 * 64);
    const float* p = qkv + (size_t)s * QKVW + hh * HDIM;
    float x1 = p[d], x2 = p[d + 64];
    float c  = cosT[s * HDIM + d];
    float sn = sinT[s * HDIM + d];
    float y1 = fmaf(x1, c, -x2 * sn);
    float y2 = fmaf(x2, c,  x1 * sn);
    __half h1 = __float2half_rn(y1), h2 = __float2half_rn(y2);
    if (hh < NH) {
        size_t o = (size_t)s * QW + hh * HDIM;
        qhi[o + d] = h1; qhi[o + d + 64] = h2;
    } else {
        size_t o = (size_t)s * KWW + (hh - NH) * HDIM;
        khi[o + d] = h1; khi[o + d + 64] = h2;
    }
}

__global__ void split_v(const float* __restrict__ qkv,
                        __half* __restrict__ vhi)
{
    int idx = blockIdx.x * blockDim.x + threadIdx.x;
    if (idx >= SEQ * KWW) return;
    int c = idx & (KWW - 1);
    int s = idx >> 9;
    vhi[(size_t)s * KWW + c] =
        __float2half_rn(qkv[(size_t)s * QKVW + QW + KWW + c]);
}

// ============================================================================
// Tensor-core causal flash attention — pure fp16 operands, fp32 softmax/accum.
// CTA = 128 q-rows x head, 8 warps x 16 rows. KV super-tiles 128 rows
// double-buffered; two 64-col sub-tiles per stage.
// ============================================================================
#define BQ      128
#define BKVO    128
#define FL_STR  136
#define FL_QT   (BQ * FL_STR * 2)              /* 34816 */
#define FL_KT   (BKVO * FL_STR * 2)            /* 34816 */
#define FL_STG  (2 * FL_KT)                    /* 69632 */
#define FLASH_SMEM (FL_QT + 2 * FL_STG)        /* 174080 */

__global__ __launch_bounds__(256, 1) void flash_mma(
    const __half* __restrict__ Qhi,
    const __half* __restrict__ Khi, const __half* __restrict__ Vhi,
    __half* __restrict__ Ohi)
{
    extern __shared__ char smem[];
    const uint32_t sbm = smem_u32(smem);
    const uint32_t QHI = sbm;
    const uint32_t ST0 = sbm + FL_QT;

    const int qt  = (int)gridDim.x - 1 - (int)blockIdx.x;
    const int h   = blockIdx.y;
    const int kvh = h >> 2;
    const int tid = threadIdx.x, wid = tid >> 5, lane = tid & 31;
    const int qbase = qt * BQ;
    const int wm  = wid * 16;
    const int nkt = qt + 1;
    const float scale = 0.08838834764831845f;

    const int a_row = lane & 15;
    const int a_cb  = ((lane >> 4) & 1) << 3;
    const int b_row = (lane & 7) + (((lane >> 4) & 1) << 3);
    const int b_cb  = ((lane >> 3) & 1) << 3;
    const int v_row = (lane & 7) + (((lane >> 3) & 1) << 3);
    const int v_cb  = ((lane >> 4) & 1) << 3;
    const int r0    = lane >> 2;
    const int colq  = (lane & 3) * 2;

    // ---- Q tile -> smem ----
    {
        const size_t qoff = (size_t)qbase * QW + h * HDIM;
#pragma unroll
        for (int it = 0; it < 8; it++) {
            int idx = tid + it * 256;
            int r = idx >> 4, c = idx & 15;
            cp16(QHI + (uint32_t)(r * FL_STR + c * 8) * 2,
                 Qhi + qoff + (size_t)r * QW + c * 8);
        }
        CP_COMMIT();
    }

#define FL_LOAD(s, kb) do {                                                   \
    uint32_t stb_ = ST0 + (uint32_t)(s) * FL_STG;                             \
    const size_t ko_ = (size_t)(kb) * KWW + kvh * HDIM;                       \
    _Pragma("unroll")                                                         \
    for (int it = 0; it < 8; it++) {                                          \
        int idx = tid + it * 256;                                             \
        int r = idx >> 4, c = idx & 15;                                       \
        uint32_t d_ = (uint32_t)(r * FL_STR + c * 8) * 2;                     \
        const size_t so_ = ko_ + (size_t)r * KWW + c * 8;                     \
        cp16(stb_ + 0 * FL_KT + d_, Khi + so_);                               \
        cp16(stb_ + 1 * FL_KT + d_, Vhi + so_);                               \
    }                                                                         \
    CP_COMMIT();                                                              \
} while (0)

    FL_LOAD(0, 0);

    // ---- cache Q fragments in registers ----
    uint32_t qh[8][4];
    CP_WAIT(1);
    __syncthreads();
#pragma unroll
    for (int ks = 0; ks < 8; ks++) {
        uint32_t qoff = (uint32_t)((wm + a_row) * FL_STR + ks * 16 + a_cb) * 2;
        LDSM4(qh[ks], QHI + qoff);
    }

    float m0 = -1e30f, m1 = -1e30f, l0 = 0.f, l1 = 0.f;
    float o[16][4];
#pragma unroll
    for (int j = 0; j < 16; j++)
#pragma unroll
        for (int q = 0; q < 4; q++) o[j][q] = 0.f;

    for (int kt = 0; kt < nkt; kt++) {
        if (kt + 1 < nkt) { FL_LOAD((kt + 1) & 1, (kt + 1) * BKVO); CP_WAIT(1); }
        else              { CP_WAIT(0); }
        __syncthreads();

        const uint32_t stb = ST0 + (uint32_t)(kt & 1) * FL_STG;

#pragma unroll
        for (int sub = 0; sub < 2; sub++) {
            const uint32_t KH = stb + (uint32_t)(sub * 64 * FL_STR * 2);
            const uint32_t VH = stb + FL_KT + (uint32_t)(sub * 64 * FL_STR * 2);
            const int kbase = kt * BKVO + sub * 64;

            // ---- S = Q K^T (single-term fp16) ----
            float s[8][4];
#pragma unroll
            for (int j = 0; j < 8; j++)
#pragma unroll
                for (int q = 0; q < 4; q++) s[j][q] = 0.f;

#pragma unroll
            for (int ks = 0; ks < 8; ks++) {
#pragma unroll
                for (int jp = 0; jp < 4; jp++) {
                    uint32_t bh[4];
                    uint32_t koff = (uint32_t)((jp * 16 + b_row) * FL_STR
                                               + ks * 16 + b_cb) * 2;
                    LDSM4(bh, KH + koff);
                    MMA16816(s[2*jp],   qh[ks], bh);
                    MMA16816(s[2*jp+1], qh[ks], bh + 2);
                }
            }

            // ---- softmax ----
            if (kbase + 63 > qbase + wm) {
                const int row0g = qbase + wm + r0, row1g = row0g + 8;
#pragma unroll
                for (int j = 0; j < 8; j++) {
                    int c0 = kbase + j * 8 + colq, c1 = c0 + 1;
                    s[j][0] = (c0 <= row0g) ? s[j][0] * scale : -1e30f;
                    s[j][1] = (c1 <= row0g) ? s[j][1] * scale : -1e30f;
                    s[j][2] = (c0 <= row1g) ? s[j][2] * scale : -1e30f;
                    s[j][3] = (c1 <= row1g) ? s[j][3] * scale : -1e30f;
                }
            } else {
#pragma unroll
                for (int j = 0; j < 8; j++) {
                    s[j][0] *= scale; s[j][1] *= scale;
                    s[j][2] *= scale; s[j][3] *= scale;
                }
            }

            float rmax0 = -1e30f, rmax1 = -1e30f;
#pragma unroll
            for (int j = 0; j < 8; j++) {
                rmax0 = fmaxf(rmax0, fmaxf(s[j][0], s[j][1]));
                rmax1 = fmaxf(rmax1, fmaxf(s[j][2], s[j][3]));
            }
            rmax0 = fmaxf(rmax0, __shfl_xor_sync(0xffffffffu, rmax0, 1));
            rmax0 = fmaxf(rmax0, __shfl_xor_sync(0xffffffffu, rmax0, 2));
            rmax1 = fmaxf(rmax1, __shfl_xor_sync(0xffffffffu, rmax1, 1));
            rmax1 = fmaxf(rmax1, __shfl_xor_sync(0xffffffffu, rmax1, 2));

            float mn0 = fmaxf(m0, rmax0), mn1 = fmaxf(m1, rmax1);
            float al0 = __expf(m0 - mn0), al1 = __expf(m1 - mn1);
            m0 = mn0; m1 = mn1;

            float rs0 = 0.f, rs1 = 0.f;
#pragma unroll
            for (int j = 0; j < 8; j++) {
                s[j][0] = __expf(s[j][0] - mn0); rs0 += s[j][0];
                s[j][1] = __expf(s[j][1] - mn0); rs0 += s[j][1];
                s[j][2] = __expf(s[j][2] - mn1); rs1 += s[j][2];
                s[j][3] = __expf(s[j][3] - mn1); rs1 += s[j][3];
            }
            rs0 += __shfl_xor_sync(0xffffffffu, rs0, 1);
            rs0 += __shfl_xor_sync(0xffffffffu, rs0, 2);
            rs1 += __shfl_xor_sync(0xffffffffu, rs1, 1);
            rs1 += __shfl_xor_sync(0xffffffffu, rs1, 2);
            l0 = l0 * al0 + rs0;
            l1 = l1 * al1 + rs1;

#pragma unroll
            for (int j = 0; j < 16; j++) {
                o[j][0] *= al0; o[j][1] *= al0;
                o[j][2] *= al1; o[j][3] *= al1;
            }

            // ---- O += P V (single-term) ----
#pragma unroll
            for (int t = 0; t < 4; t++) {
                uint32_t ph[4];
                ph[0] = hpack2(s[2*t][0],   s[2*t][1]);
                ph[1] = hpack2(s[2*t][2],   s[2*t][3]);
                ph[2] = hpack2(s[2*t+1][0], s[2*t+1][1]);
                ph[3] = hpack2(s[2*t+1][2], s[2*t+1][3]);
#pragma unroll
                for (int jp = 0; jp < 8; jp++) {
                    uint32_t vh[4];
                    uint32_t voff = (uint32_t)((t * 16 + v_row) * FL_STR
                                               + jp * 16 + v_cb) * 2;
                    LDSM4T(vh, VH + voff);
                    MMA16816(o[2*jp],   ph, vh);
                    MMA16816(o[2*jp+1], ph, vh + 2);
                }
            }
        }
        __syncthreads();
    }

    const float inv0 = 1.f / l0, inv1 = 1.f / l1;
    const int row0g = qbase + wm + r0;
    const size_t base0 = (size_t)row0g * QW + h * HDIM;
    const size_t base1 = base0 + (size_t)8 * QW;
#pragma unroll
    for (int j = 0; j < 16; j++) {
        int col = j * 8 + colq;
        *(uint32_t*)(Ohi + base0 + col) = hpack2(o[j][0] * inv0, o[j][1] * inv0);
        *(uint32_t*)(Ohi + base1 + col) = hpack2(o[j][2] * inv1, o[j][3] * inv1);
    }
}

// ============================================================================
// Launch
// ============================================================================
extern "C" void kernel_launch(void* const* d_in, const int* in_sizes, int n_in,
                              void* d_out, int out_size)
{
    const float* hidden = (const float*)d_in[0];
    const float* cosT   = (const float*)d_in[1];
    const float* sinT   = (const float*)d_in[2];
    const float* wq     = (const float*)d_in[4];
    const float* wk     = (const float*)d_in[5];
    const float* wv     = (const float*)d_in[6];
    const float* wo     = (const float*)d_in[7];
    float* out = (float*)d_out;

    float* qkv;
    __half *h_hi, *w_hi, *wo_hi;
    __half *q_hi, *k_hi, *v_hi, *a_hi;
    cudaGetSymbolAddress((void**)&qkv,   g_qkv);
    cudaGetSymbolAddress((void**)&h_hi,  g_h_hi);
    cudaGetSymbolAddress((void**)&w_hi,  g_w_hi);
    cudaGetSymbolAddress((void**)&wo_hi, g_wo_hi);
    cudaGetSymbolAddress((void**)&q_hi,  g_q_hi);
    cudaGetSymbolAddress((void**)&k_hi,  g_k_hi);
    cudaGetSymbolAddress((void**)&v_hi,  g_v_hi);
    cudaGetSymbolAddress((void**)&a_hi,  g_a_hi);

    cudaFuncSetAttribute(gemm_f16,
                         cudaFuncAttributeMaxDynamicSharedMemorySize, GEMM_SMEM);
    cudaFuncSetAttribute(flash_mma,
                         cudaFuncAttributeMaxDynamicSharedMemorySize, FLASH_SMEM);

    conv_h<<<(SEQ * DM / 4 + 255) / 256, 256>>>(hidden, h_hi, SEQ * DM);
    conv_w_fused<<<(N_WTOT / 4 + 255) / 256, 256>>>(wq, wk, wv, wo, w_hi, wo_hi);

    gemm_f16<<<dim3(QKVW / 256, SEQ / 128), 256, GEMM_SMEM>>>(
        h_hi, w_hi, qkv, QKVW, DM);

    rope_conv_qk<<<(SEQ * 20 * 64 + 255) / 256, 256>>>(
        qkv, cosT, sinT, q_hi, k_hi);
    split_v<<<(SEQ * KWW + 255) / 256, 256>>>(qkv, v_hi);

    flash_mma<<<dim3(SEQ / BQ, NH), 256, FLASH_SMEM>>>(
        q_hi, k_hi, v_hi, a_hi);

    gemm_f16<<<dim3(DM / 256, SEQ / 128), 256, GEMM_SMEM>>>(
        a_hi, wo_hi, out, DM, DM);
}